// round 2
// baseline (speedup 1.0000x reference)
#include <cuda_runtime.h>
#include <cstddef>

#define N_MAX 131072
#define HID 128

// Scratch (allocation-free rule: __device__ globals)
__device__ float g_act[(size_t)N_MAX * HID];
__device__ float g_tmp[(size_t)N_MAX * HID];

// ---------------------------------------------------------------------------
// Classic 128x128x8 fp32 SGEMM, relu applied to A on load.
// C[n,128] = relu(A[n,K]) @ B[K,128] + bias (+ resid)
// grid = n/128, block = 256
// ---------------------------------------------------------------------------
template <bool HAS_RES>
__global__ void __launch_bounds__(256, 2) sgemm128(
    const float* __restrict__ A, int lda, int K,
    const float* __restrict__ B,
    const float* __restrict__ bias,
    const float* __restrict__ resid,
    float* __restrict__ C)
{
    __shared__ float As[8][128];
    __shared__ float Bs[8][128];

    const int tid = threadIdx.x;
    const int tx = tid & 15;
    const int ty = tid >> 4;
    const int row0 = blockIdx.x * 128;

    const int arow = tid >> 1;        // 0..127
    const int acol = (tid & 1) * 4;   // 0 or 4
    const int brow = tid >> 5;        // 0..7
    const int bcol = (tid & 31) * 4;  // 0..124

    const float* Aptr = A + (size_t)(row0 + arow) * lda + acol;

    float acc[8][8];
#pragma unroll
    for (int i = 0; i < 8; i++)
#pragma unroll
        for (int j = 0; j < 8; j++) acc[i][j] = 0.f;

    for (int k0 = 0; k0 < K; k0 += 8) {
        float4 av = *(const float4*)(Aptr + k0);
        av.x = fmaxf(av.x, 0.f); av.y = fmaxf(av.y, 0.f);
        av.z = fmaxf(av.z, 0.f); av.w = fmaxf(av.w, 0.f);
        As[acol + 0][arow] = av.x;
        As[acol + 1][arow] = av.y;
        As[acol + 2][arow] = av.z;
        As[acol + 3][arow] = av.w;
        *(float4*)&Bs[brow][bcol] = *(const float4*)(B + (size_t)(k0 + brow) * 128 + bcol);
        __syncthreads();

#pragma unroll
        for (int kk = 0; kk < 8; kk++) {
            float a[8], b[8];
            *(float4*)(a)     = *(const float4*)&As[kk][ty * 8];
            *(float4*)(a + 4) = *(const float4*)&As[kk][ty * 8 + 4];
            *(float4*)(b)     = *(const float4*)&Bs[kk][tx * 8];
            *(float4*)(b + 4) = *(const float4*)&Bs[kk][tx * 8 + 4];
#pragma unroll
            for (int i = 0; i < 8; i++)
#pragma unroll
                for (int j = 0; j < 8; j++) acc[i][j] += a[i] * b[j];
        }
        __syncthreads();
    }

#pragma unroll
    for (int i = 0; i < 8; i++) {
        const int row = row0 + ty * 8 + i;
        float* Crow = C + (size_t)row * 128 + tx * 8;
#pragma unroll
        for (int j = 0; j < 8; j++) {
            float v = acc[i][j] + bias[tx * 8 + j];
            if (HAS_RES) v += resid[(size_t)row * 128 + tx * 8 + j];
            Crow[j] = v;
        }
    }
}

// ---------------------------------------------------------------------------
// Input GEMM: act = relu(rep0)@w0 + relu(rep1)@w1 + b0 + b1
// Treated as K=768 concat.  grid = n/128, block = 256
// ---------------------------------------------------------------------------
__global__ void __launch_bounds__(256, 2) sgemm_input(
    const float* __restrict__ rep0, const float* __restrict__ rep1,
    const float* __restrict__ w0, const float* __restrict__ w1,
    const float* __restrict__ b0, const float* __restrict__ b1,
    float* __restrict__ C)
{
    __shared__ float As[8][128];
    __shared__ float Bs[8][128];

    const int tid = threadIdx.x;
    const int tx = tid & 15;
    const int ty = tid >> 4;
    const int row0 = blockIdx.x * 128;

    const int arow = tid >> 1;
    const int acol = (tid & 1) * 4;
    const int brow = tid >> 5;
    const int bcol = (tid & 31) * 4;

    float acc[8][8];
#pragma unroll
    for (int i = 0; i < 8; i++)
#pragma unroll
        for (int j = 0; j < 8; j++) acc[i][j] = 0.f;

#pragma unroll 1
    for (int phase = 0; phase < 2; phase++) {
        const float* A = phase ? rep1 : rep0;
        const float* B = phase ? w1 : w0;
        const float* Aptr = A + (size_t)(row0 + arow) * 384 + acol;
        for (int k0 = 0; k0 < 384; k0 += 8) {
            float4 av = *(const float4*)(Aptr + k0);
            av.x = fmaxf(av.x, 0.f); av.y = fmaxf(av.y, 0.f);
            av.z = fmaxf(av.z, 0.f); av.w = fmaxf(av.w, 0.f);
            As[acol + 0][arow] = av.x;
            As[acol + 1][arow] = av.y;
            As[acol + 2][arow] = av.z;
            As[acol + 3][arow] = av.w;
            *(float4*)&Bs[brow][bcol] = *(const float4*)(B + (size_t)(k0 + brow) * 128 + bcol);
            __syncthreads();
#pragma unroll
            for (int kk = 0; kk < 8; kk++) {
                float a[8], b[8];
                *(float4*)(a)     = *(const float4*)&As[kk][ty * 8];
                *(float4*)(a + 4) = *(const float4*)&As[kk][ty * 8 + 4];
                *(float4*)(b)     = *(const float4*)&Bs[kk][tx * 8];
                *(float4*)(b + 4) = *(const float4*)&Bs[kk][tx * 8 + 4];
#pragma unroll
                for (int i = 0; i < 8; i++)
#pragma unroll
                    for (int j = 0; j < 8; j++) acc[i][j] += a[i] * b[j];
            }
            __syncthreads();
        }
    }

#pragma unroll
    for (int i = 0; i < 8; i++) {
        const int row = row0 + ty * 8 + i;
        float* Crow = C + (size_t)row * 128 + tx * 8;
#pragma unroll
        for (int j = 0; j < 8; j++)
            Crow[j] = acc[i][j] + b0[tx * 8 + j] + b1[tx * 8 + j];
    }
}

// ---------------------------------------------------------------------------
// Per-residue epilogue: angles GEMV + normalize + rigid-frame geometry.
// One thread per residue, 64 residues per block.
// ---------------------------------------------------------------------------
__global__ void __launch_bounds__(64) epilogue_kernel(
    const float* __restrict__ act,
    const float* __restrict__ affine,
    const int* __restrict__ aatype,
    const float* __restrict__ w_ang,
    const float* __restrict__ b_ang,
    const float* __restrict__ frames,
    const int* __restrict__ gidx,
    const float* __restrict__ amask,
    const float* __restrict__ lit,
    float* __restrict__ out,
    int n)
{
    __shared__ float sAct[64][129];
    __shared__ float sW[128 * 14];
    __shared__ float sB[14];

    const int tid = threadIdx.x;
    const int r0 = blockIdx.x * 64;

    for (int idx = tid; idx < 128 * 14; idx += 64) sW[idx] = w_ang[idx];
    if (tid < 14) sB[tid] = b_ang[tid];
    for (int idx = tid; idx < 64 * 128; idx += 64) {
        int rr = idx >> 7, cc = idx & 127;
        sAct[rr][cc] = fmaxf(act[(size_t)(r0 + rr) * 128 + cc], 0.f);
    }
    __syncthreads();

    const int r = r0 + tid;
    if (r >= n) return;

    // --- unnorm = relu(act) @ w_ang + b_ang ---
    float u[14];
#pragma unroll
    for (int j = 0; j < 14; j++) u[j] = sB[j];
    for (int k = 0; k < 128; k++) {
        float a = sAct[tid][k];
#pragma unroll
        for (int j = 0; j < 14; j++) u[j] += a * sW[k * 14 + j];
    }

    const size_t nsz = (size_t)n;
    float* out_ang = out;
    float* out_un  = out + nsz * 14;
    float* out_pos = out + nsz * 28;
    float* out_rg  = out + nsz * 70;
    float* out_tg  = out + nsz * 142;

    // --- angles = l2_normalize(unnorm) ---
    float sv[8], cv[8];
    sv[0] = 0.f; cv[0] = 1.f;
#pragma unroll
    for (int g = 0; g < 7; g++) {
        float s0 = u[2 * g], c0 = u[2 * g + 1];
        float inv = rsqrtf(fmaxf(s0 * s0 + c0 * c0, 1e-12f));
        float a0 = s0 * inv, a1 = c0 * inv;
        out_ang[(size_t)r * 14 + 2 * g]     = a0;
        out_ang[(size_t)r * 14 + 2 * g + 1] = a1;
        sv[g + 1] = a0;
        cv[g + 1] = a1;
    }
#pragma unroll
    for (int j = 0; j < 14; j++) out_un[(size_t)r * 14 + j] = u[j];

    // --- backbone rotation from quaternion ---
    const float* af = affine + (size_t)r * 7;
    float qw = af[0], qx = af[1], qy = af[2], qz = af[3];
    float qinv = rsqrtf(fmaxf(qw * qw + qx * qx + qy * qy + qz * qz, 1e-12f));
    qw *= qinv; qx *= qinv; qy *= qinv; qz *= qinv;
    float rb[3][3];
    rb[0][0] = 1.f - 2.f * (qy * qy + qz * qz);
    rb[0][1] = 2.f * (qx * qy - qw * qz);
    rb[0][2] = 2.f * (qx * qz + qw * qy);
    rb[1][0] = 2.f * (qx * qy + qw * qz);
    rb[1][1] = 1.f - 2.f * (qx * qx + qz * qz);
    rb[1][2] = 2.f * (qy * qz - qw * qx);
    rb[2][0] = 2.f * (qx * qz - qw * qy);
    rb[2][1] = 2.f * (qy * qz + qw * qx);
    rb[2][2] = 1.f - 2.f * (qx * qx + qy * qy);
    const float tb0 = af[4], tb1 = af[5], tb2 = af[6];

    const int at = aatype[r];
    const float* mf = frames + (size_t)at * 128;  // 8 frames * 16

    // rot_f = m[:3,:3] @ all_rots ; trans_f = m[:3,3]
    float rf[8][3][3], tf[8][3];
#pragma unroll
    for (int g = 0; g < 8; g++) {
#pragma unroll
        for (int i = 0; i < 3; i++) {
            float m0 = mf[g * 16 + i * 4 + 0];
            float m1 = mf[g * 16 + i * 4 + 1];
            float m2 = mf[g * 16 + i * 4 + 2];
            float m3 = mf[g * 16 + i * 4 + 3];
            rf[g][i][0] = m0;
            rf[g][i][1] = m1 * cv[g] + m2 * sv[g];
            rf[g][i][2] = -m1 * sv[g] + m2 * cv[g];
            tf[g][i] = m3;
        }
    }

    // compose chain: frames 5,6,7 build on the previous
#pragma unroll
    for (int g = 5; g < 8; g++) {
        float R[3][3], T[3];
#pragma unroll
        for (int i = 0; i < 3; i++) {
#pragma unroll
            for (int j = 0; j < 3; j++)
                R[i][j] = rf[g - 1][i][0] * rf[g][0][j]
                        + rf[g - 1][i][1] * rf[g][1][j]
                        + rf[g - 1][i][2] * rf[g][2][j];
            T[i] = rf[g - 1][i][0] * tf[g][0]
                 + rf[g - 1][i][1] * tf[g][1]
                 + rf[g - 1][i][2] * tf[g][2] + tf[g - 1][i];
        }
#pragma unroll
        for (int i = 0; i < 3; i++) {
#pragma unroll
            for (int j = 0; j < 3; j++) rf[g][i][j] = R[i][j];
            tf[g][i] = T[i];
        }
    }

    // per-atom metadata
    int ga[14];
    float mk[14];
    float lp[14][3];
#pragma unroll
    for (int a = 0; a < 14; a++) {
        ga[a] = gidx[at * 14 + a];
        mk[a] = amask[at * 14 + a];
        lp[a][0] = lit[((size_t)at * 14 + a) * 3 + 0];
        lp[a][1] = lit[((size_t)at * 14 + a) * 3 + 1];
        lp[a][2] = lit[((size_t)at * 14 + a) * 3 + 2];
    }

    float pos[14][3];
#pragma unroll
    for (int a = 0; a < 14; a++) { pos[a][0] = 0.f; pos[a][1] = 0.f; pos[a][2] = 0.f; }

    // rot_g = rb @ rf ; trans_g = rb @ tf + tb ; then scatter atoms
#pragma unroll
    for (int g = 0; g < 8; g++) {
        float R[3][3], T[3];
#pragma unroll
        for (int i = 0; i < 3; i++) {
#pragma unroll
            for (int j = 0; j < 3; j++)
                R[i][j] = rb[i][0] * rf[g][0][j] + rb[i][1] * rf[g][1][j] + rb[i][2] * rf[g][2][j];
        }
        T[0] = rb[0][0] * tf[g][0] + rb[0][1] * tf[g][1] + rb[0][2] * tf[g][2] + tb0;
        T[1] = rb[1][0] * tf[g][0] + rb[1][1] * tf[g][1] + rb[1][2] * tf[g][2] + tb1;
        T[2] = rb[2][0] * tf[g][0] + rb[2][1] * tf[g][1] + rb[2][2] * tf[g][2] + tb2;

#pragma unroll
        for (int i = 0; i < 3; i++) {
#pragma unroll
            for (int j = 0; j < 3; j++)
                out_rg[(size_t)r * 72 + g * 9 + i * 3 + j] = R[i][j];
            out_tg[(size_t)r * 24 + g * 3 + i] = T[i];
        }

#pragma unroll
        for (int a = 0; a < 14; a++) {
            if (ga[a] == g) {
                pos[a][0] = R[0][0] * lp[a][0] + R[0][1] * lp[a][1] + R[0][2] * lp[a][2] + T[0];
                pos[a][1] = R[1][0] * lp[a][0] + R[1][1] * lp[a][1] + R[1][2] * lp[a][2] + T[1];
                pos[a][2] = R[2][0] * lp[a][0] + R[2][1] * lp[a][1] + R[2][2] * lp[a][2] + T[2];
            }
        }
    }

#pragma unroll
    for (int a = 0; a < 14; a++) {
        out_pos[(size_t)r * 42 + a * 3 + 0] = pos[a][0] * mk[a];
        out_pos[(size_t)r * 42 + a * 3 + 1] = pos[a][1] * mk[a];
        out_pos[(size_t)r * 42 + a * 3 + 2] = pos[a][2] * mk[a];
    }
}

// ---------------------------------------------------------------------------
extern "C" void kernel_launch(void* const* d_in, const int* in_sizes, int n_in,
                              void* d_out, int out_size)
{
    const float* affine = (const float*)d_in[0];
    const float* rep0   = (const float*)d_in[1];
    const float* rep1   = (const float*)d_in[2];
    const int*   aatype = (const int*)d_in[3];
    const float* w_in0  = (const float*)d_in[4];
    const float* b_in0  = (const float*)d_in[5];
    const float* w_in1  = (const float*)d_in[6];
    const float* b_in1  = (const float*)d_in[7];
    const float* Wr1    = (const float*)d_in[8];
    const float* br1    = (const float*)d_in[9];
    const float* Wr2    = (const float*)d_in[10];
    const float* br2    = (const float*)d_in[11];
    const float* w_ang  = (const float*)d_in[12];
    const float* b_ang  = (const float*)d_in[13];
    const float* frames = (const float*)d_in[14];
    const int*   gidx   = (const int*)d_in[15];
    const float* amask  = (const float*)d_in[16];
    const float* lit    = (const float*)d_in[17];
    float* out = (float*)d_out;

    const int n = in_sizes[0] / 7;

    float *act = nullptr, *tmp = nullptr;
    cudaGetSymbolAddress((void**)&act, g_act);
    cudaGetSymbolAddress((void**)&tmp, g_tmp);

    const int gblocks = n / 128;

    // act = relu(rep0)@w_in0 + relu(rep1)@w_in1 + b_in0 + b_in1
    sgemm_input<<<gblocks, 256>>>(rep0, rep1, w_in0, w_in1, b_in0, b_in1, act);

    // resnet blocks
    for (int i = 0; i < 2; i++) {
        sgemm128<false><<<gblocks, 256>>>(act, 128, 128, Wr1 + (size_t)i * 128 * 128,
                                          br1 + (size_t)i * 128, nullptr, tmp);
        sgemm128<true><<<gblocks, 256>>>(tmp, 128, 128, Wr2 + (size_t)i * 128 * 128,
                                         br2 + (size_t)i * 128, act, act);
    }

    // per-residue geometry
    epilogue_kernel<<<(n + 63) / 64, 64>>>(act, affine, aatype, w_ang, b_ang,
                                           frames, gidx, amask, lit, out, n);
}

// round 4
// speedup vs baseline: 2.0698x; 2.0698x over previous
#include <cuda_runtime.h>
#include <cuda_bf16.h>
#include <cstdint>
#include <cstddef>

#define N_MAX 131072

// Scratch (allocation-free rule: __device__ globals)
__device__ float g_act[(size_t)N_MAX * 128];
// 10 weight tiles x {hi,lo} x 16384 bf16, layout [n][k] (n-major), unpadded
__device__ __nv_bfloat16 g_wpk[10 * 2 * 16384];

// ---------------------------------------------------------------------------
// PTX helpers
// ---------------------------------------------------------------------------
__device__ __forceinline__ uint32_t smem_u32(const void* p) {
    uint32_t a;
    asm("{ .reg .u64 t; cvta.to.shared.u64 t, %1; cvt.u32.u64 %0, t; }" : "=r"(a) : "l"(p));
    return a;
}
__device__ __forceinline__ void ldsm_x4(uint32_t addr, uint32_t* r) {
    asm volatile("ldmatrix.sync.aligned.m8n8.x4.shared.b16 {%0,%1,%2,%3}, [%4];"
        : "=r"(r[0]), "=r"(r[1]), "=r"(r[2]), "=r"(r[3]) : "r"(addr));
}
__device__ __forceinline__ void mma16816(float* d, const uint32_t* a, uint32_t b0, uint32_t b1) {
    asm volatile(
        "mma.sync.aligned.m16n8k16.row.col.f32.bf16.bf16.f32 "
        "{%0,%1,%2,%3}, {%4,%5,%6,%7}, {%8,%9}, {%0,%1,%2,%3};"
        : "+f"(d[0]), "+f"(d[1]), "+f"(d[2]), "+f"(d[3])
        : "r"(a[0]), "r"(a[1]), "r"(a[2]), "r"(a[3]), "r"(b0), "r"(b1));
}
__device__ __forceinline__ uint32_t packbf(float a, float b) {
    __nv_bfloat162 h = __floats2bfloat162_rn(a, b);
    return *reinterpret_cast<uint32_t*>(&h);
}

// ---------------------------------------------------------------------------
// Weight pack: [k][n] fp32 -> [n][k] bf16 hi/lo split.
// tile 0-2: w_in0 k-chunks; 3-5: w_in1; 6: Wr1[0]; 7: Wr2[0]; 8: Wr1[1]; 9: Wr2[1]
// ---------------------------------------------------------------------------
__global__ void pack_weights(const float* __restrict__ w_in0, const float* __restrict__ w_in1,
                             const float* __restrict__ Wr1, const float* __restrict__ Wr2)
{
    int tile = blockIdx.x;
    const float* W;
    if (tile < 3)       W = w_in0 + (size_t)tile * 16384;
    else if (tile < 6)  W = w_in1 + (size_t)(tile - 3) * 16384;
    else if (tile == 6) W = Wr1;
    else if (tile == 7) W = Wr2;
    else if (tile == 8) W = Wr1 + 16384;
    else                W = Wr2 + 16384;
    __nv_bfloat16* hi_out = g_wpk + (size_t)tile * 2 * 16384;
    __nv_bfloat16* lo_out = hi_out + 16384;
    for (int i = threadIdx.x; i < 16384; i += blockDim.x) {
        int k = i >> 7, nn = i & 127;
        float v = W[(size_t)k * 128 + nn];
        __nv_bfloat16 h = __float2bfloat16(v);
        float lo = v - __bfloat162float(h);
        hi_out[nn * 128 + k] = h;
        lo_out[nn * 128 + k] = __float2bfloat16(lo);
    }
}

// ---------------------------------------------------------------------------
// Fused MLP on mma.sync bf16 (3-term split emulation of fp32).
// One 128-row tile per CTA, 256 threads (8 warps: 4m x 2n, 32x64 per warp).
// SMEM tiles padded to stride 136 bf16 (272 B) for conflict-free ldmatrix.
// ---------------------------------------------------------------------------
#define LDT        136                      // padded stride in bf16 elems
#define TILE_B     (128 * LDT * 2)          // 34816 bytes per tile
#define A_HI_OFF   0
#define A_LO_OFF   (TILE_B)
#define B_HI_OFF   (2 * TILE_B)
#define B_LO_OFF   (3 * TILE_B)
#define STAGE_OFF  (4 * TILE_B)             // float[128][129]
#define SMEM_TOTAL (4 * TILE_B + 128 * 129 * 4)

struct Frags { float acc[2][8][4]; };

__device__ __forceinline__ void gemm_k128(
    uint32_t aHi, uint32_t aLo, uint32_t bHi, uint32_t bLo,
    uint32_t aoff0, uint32_t aoff1, const uint32_t* boff,
    float acc[2][8][4])
{
#pragma unroll
    for (int ks = 0; ks < 8; ks++) {
        const uint32_t kb2 = ks * 32;  // 16 elems * 2 bytes
        uint32_t ah[2][4], al[2][4], bh[4][4], bl[4][4];
        ldsm_x4(aHi + aoff0 + kb2, ah[0]);
        ldsm_x4(aHi + aoff1 + kb2, ah[1]);
        ldsm_x4(aLo + aoff0 + kb2, al[0]);
        ldsm_x4(aLo + aoff1 + kb2, al[1]);
#pragma unroll
        for (int p = 0; p < 4; p++) {
            ldsm_x4(bHi + boff[p] + kb2, bh[p]);
            ldsm_x4(bLo + boff[p] + kb2, bl[p]);
        }
#pragma unroll
        for (int i = 0; i < 2; i++)
#pragma unroll
            for (int p = 0; p < 4; p++)
#pragma unroll
                for (int h = 0; h < 2; h++) {
                    float* d = acc[i][2 * p + h];
                    mma16816(d, ah[i], bh[p][2 * h], bh[p][2 * h + 1]);
                    mma16816(d, ah[i], bl[p][2 * h], bl[p][2 * h + 1]);
                    mma16816(d, al[i], bh[p][2 * h], bh[p][2 * h + 1]);
                }
    }
}

__global__ void __launch_bounds__(256, 1) fused_mlp(
    const float* __restrict__ rep0, const float* __restrict__ rep1,
    const float* __restrict__ b_in0, const float* __restrict__ b_in1,
    const float* __restrict__ br1, const float* __restrict__ br2,
    float* __restrict__ act_out)
{
    extern __shared__ char smem[];
    char* A_hi = smem + A_HI_OFF;
    char* A_lo = smem + A_LO_OFF;
    float* stage = (float*)(smem + STAGE_OFF);

    const int tid = threadIdx.x;
    const int wid = tid >> 5;
    const int lane = tid & 31;
    const int wm = wid & 3;        // 0..3 (m)
    const int wn = wid >> 2;       // 0..1 (n)
    const int row0 = blockIdx.x * 128;

    const uint32_t sb = smem_u32(smem);
    const uint32_t aHi = sb + A_HI_OFF;
    const uint32_t aLo = sb + A_LO_OFF;
    const uint32_t bHi = sb + B_HI_OFF;
    const uint32_t bLo = sb + B_LO_OFF;

    // per-thread ldmatrix byte offsets
    const uint32_t aoff0 = ((wm * 32 + (lane & 15)) * LDT + ((lane >> 4) << 3)) * 2;
    const uint32_t aoff1 = aoff0 + 16 * LDT * 2;
    uint32_t boff[4];
#pragma unroll
    for (int p = 0; p < 4; p++)
        boff[p] = ((wn * 64 + p * 16 + (lane & 7) + ((lane >> 4) << 3)) * LDT
                   + (((lane >> 3) & 1) << 3)) * 2;

    // epilogue per-thread coordinates
    const int ep_r0 = wm * 32 + (lane >> 2);      // + i*16, + 8
    const int ep_c0 = wn * 64 + (lane & 3) * 2;   // + j*8

    float acc[2][8][4];
#pragma unroll
    for (int i = 0; i < 2; i++)
#pragma unroll
        for (int j = 0; j < 8; j++)
#pragma unroll
            for (int q = 0; q < 4; q++) acc[i][j][q] = 0.f;

    // ================= input GEMM: K = 768 (6 chunks of 128) ==============
    for (int kc = 0; kc < 6; kc++) {
        const float* src = (kc < 3) ? rep0 : rep1;
        const int kb = (kc % 3) * 128;

        // stage A chunk: relu + hi/lo split, row-major padded
        for (int i = tid; i < 4096; i += 256) {
            int r = i >> 5, c4 = (i & 31) * 4;
            float4 v = *(const float4*)(src + (size_t)(row0 + r) * 384 + kb + c4);
            v.x = fmaxf(v.x, 0.f); v.y = fmaxf(v.y, 0.f);
            v.z = fmaxf(v.z, 0.f); v.w = fmaxf(v.w, 0.f);
            __nv_bfloat16 h0 = __float2bfloat16(v.x), h1 = __float2bfloat16(v.y);
            __nv_bfloat16 h2 = __float2bfloat16(v.z), h3 = __float2bfloat16(v.w);
            uint32_t off = (r * LDT + c4) * 2;
            uint2 ph, pl;
            ph.x = packbf(__bfloat162float(h0), __bfloat162float(h1));
            ph.y = packbf(__bfloat162float(h2), __bfloat162float(h3));
            pl.x = packbf(v.x - __bfloat162float(h0), v.y - __bfloat162float(h1));
            pl.y = packbf(v.z - __bfloat162float(h2), v.w - __bfloat162float(h3));
            *(uint2*)(A_hi + off) = ph;
            *(uint2*)(A_lo + off) = pl;
        }
        // copy B chunk (hi/lo) into padded smem
        {
            const uint4* wsrc = (const uint4*)(g_wpk + (size_t)kc * 2 * 16384);
            for (int i = tid; i < 2048; i += 256) {
                int r = i >> 4, ch = i & 15;
                *(uint4*)(smem + B_HI_OFF + r * (LDT * 2) + ch * 16) = wsrc[i];
                *(uint4*)(smem + B_LO_OFF + r * (LDT * 2) + ch * 16) = wsrc[i + 2048];
            }
        }
        __syncthreads();
        gemm_k128(aHi, aLo, bHi, bLo, aoff0, aoff1, boff, acc);
        __syncthreads();
    }

    // input epilogue: act = acc + b_in0 + b_in1 -> stage, relu-split -> A
#pragma unroll
    for (int i = 0; i < 2; i++)
#pragma unroll
        for (int j = 0; j < 8; j++) {
            int c = ep_c0 + j * 8;
            float bb0 = b_in0[c] + b_in1[c];
            float bb1 = b_in0[c + 1] + b_in1[c + 1];
#pragma unroll
            for (int half = 0; half < 2; half++) {
                int r = ep_r0 + i * 16 + half * 8;
                float x0 = acc[i][j][2 * half] + bb0;
                float x1 = acc[i][j][2 * half + 1] + bb1;
                stage[r * 129 + c] = x0;
                stage[r * 129 + c + 1] = x1;
                float p0 = fmaxf(x0, 0.f), p1 = fmaxf(x1, 0.f);
                __nv_bfloat16 h0 = __float2bfloat16(p0), h1 = __float2bfloat16(p1);
                *(uint32_t*)(A_hi + (r * LDT + c) * 2) =
                    packbf(__bfloat162float(h0), __bfloat162float(h1));
                *(uint32_t*)(A_lo + (r * LDT + c) * 2) =
                    packbf(p0 - __bfloat162float(h0), p1 - __bfloat162float(h1));
            }
        }
    __syncthreads();

    // ================= resnet: 4 GEMMs (K=128) ============================
    for (int s = 0; s < 4; s++) {
        // copy weight tile
        const uint4* wsrc = (const uint4*)(g_wpk + (size_t)(6 + s) * 2 * 16384);
        for (int i = tid; i < 2048; i += 256) {
            int r = i >> 4, ch = i & 15;
            *(uint4*)(smem + B_HI_OFF + r * (LDT * 2) + ch * 16) = wsrc[i];
            *(uint4*)(smem + B_LO_OFF + r * (LDT * 2) + ch * 16) = wsrc[i + 2048];
        }
#pragma unroll
        for (int i = 0; i < 2; i++)
#pragma unroll
            for (int j = 0; j < 8; j++)
#pragma unroll
                for (int q = 0; q < 4; q++) acc[i][j][q] = 0.f;
        __syncthreads();

        gemm_k128(aHi, aLo, bHi, bLo, aoff0, aoff1, boff, acc);
        __syncthreads();

        const bool odd = (s & 1);   // second GEMM of a block: +bias2 +residual
        const bool last = (s == 3);
        const float* bias = odd ? (br2 + (s >> 1) * 128) : (br1 + (s >> 1) * 128);

#pragma unroll
        for (int i = 0; i < 2; i++)
#pragma unroll
            for (int j = 0; j < 8; j++) {
                int c = ep_c0 + j * 8;
                float bb0 = bias[c], bb1 = bias[c + 1];
#pragma unroll
                for (int half = 0; half < 2; half++) {
                    int r = ep_r0 + i * 16 + half * 8;
                    float x0 = acc[i][j][2 * half] + bb0;
                    float x1 = acc[i][j][2 * half + 1] + bb1;
                    if (odd) {
                        x0 += stage[r * 129 + c];
                        x1 += stage[r * 129 + c + 1];
                        stage[r * 129 + c] = x0;
                        stage[r * 129 + c + 1] = x1;
                    }
                    if (!last) {
                        float p0 = fmaxf(x0, 0.f), p1 = fmaxf(x1, 0.f);
                        __nv_bfloat16 h0 = __float2bfloat16(p0), h1 = __float2bfloat16(p1);
                        *(uint32_t*)(A_hi + (r * LDT + c) * 2) =
                            packbf(__bfloat162float(h0), __bfloat162float(h1));
                        *(uint32_t*)(A_lo + (r * LDT + c) * 2) =
                            packbf(p0 - __bfloat162float(h0), p1 - __bfloat162float(h1));
                    }
                }
            }
        __syncthreads();
    }

    // write final act (pre-relu, post-residual) to global
    for (int i = tid; i < 16384; i += 256) {
        int r = i >> 7, c = i & 127;
        act_out[(size_t)(row0 + r) * 128 + c] = stage[r * 129 + c];
    }
}

// ---------------------------------------------------------------------------
// Per-residue geometry epilogue (unchanged, known-correct)
// ---------------------------------------------------------------------------
__global__ void __launch_bounds__(64) epilogue_kernel(
    const float* __restrict__ act,
    const float* __restrict__ affine,
    const int* __restrict__ aatype,
    const float* __restrict__ w_ang,
    const float* __restrict__ b_ang,
    const float* __restrict__ frames,
    const int* __restrict__ gidx,
    const float* __restrict__ amask,
    const float* __restrict__ lit,
    float* __restrict__ out,
    int n)
{
    __shared__ float sAct[64][129];
    __shared__ float sW[128 * 14];
    __shared__ float sB[14];

    const int tid = threadIdx.x;
    const int r0 = blockIdx.x * 64;

    for (int idx = tid; idx < 128 * 14; idx += 64) sW[idx] = w_ang[idx];
    if (tid < 14) sB[tid] = b_ang[tid];
    for (int idx = tid; idx < 64 * 128; idx += 64) {
        int rr = idx >> 7, cc = idx & 127;
        sAct[rr][cc] = fmaxf(act[(size_t)(r0 + rr) * 128 + cc], 0.f);
    }
    __syncthreads();

    const int r = r0 + tid;
    if (r >= n) return;

    float u[14];
#pragma unroll
    for (int j = 0; j < 14; j++) u[j] = sB[j];
    for (int k = 0; k < 128; k++) {
        float a = sAct[tid][k];
#pragma unroll
        for (int j = 0; j < 14; j++) u[j] += a * sW[k * 14 + j];
    }

    const size_t nsz = (size_t)n;
    float* out_ang = out;
    float* out_un  = out + nsz * 14;
    float* out_pos = out + nsz * 28;
    float* out_rg  = out + nsz * 70;
    float* out_tg  = out + nsz * 142;

    float sv[8], cv[8];
    sv[0] = 0.f; cv[0] = 1.f;
#pragma unroll
    for (int g = 0; g < 7; g++) {
        float s0 = u[2 * g], c0 = u[2 * g + 1];
        float inv = rsqrtf(fmaxf(s0 * s0 + c0 * c0, 1e-12f));
        float a0 = s0 * inv, a1 = c0 * inv;
        out_ang[(size_t)r * 14 + 2 * g]     = a0;
        out_ang[(size_t)r * 14 + 2 * g + 1] = a1;
        sv[g + 1] = a0;
        cv[g + 1] = a1;
    }
#pragma unroll
    for (int j = 0; j < 14; j++) out_un[(size_t)r * 14 + j] = u[j];

    const float* af = affine + (size_t)r * 7;
    float qw = af[0], qx = af[1], qy = af[2], qz = af[3];
    float qinv = rsqrtf(fmaxf(qw * qw + qx * qx + qy * qy + qz * qz, 1e-12f));
    qw *= qinv; qx *= qinv; qy *= qinv; qz *= qinv;
    float rb[3][3];
    rb[0][0] = 1.f - 2.f * (qy * qy + qz * qz);
    rb[0][1] = 2.f * (qx * qy - qw * qz);
    rb[0][2] = 2.f * (qx * qz + qw * qy);
    rb[1][0] = 2.f * (qx * qy + qw * qz);
    rb[1][1] = 1.f - 2.f * (qx * qx + qz * qz);
    rb[1][2] = 2.f * (qy * qz - qw * qx);
    rb[2][0] = 2.f * (qx * qz - qw * qy);
    rb[2][1] = 2.f * (qy * qz + qw * qx);
    rb[2][2] = 1.f - 2.f * (qx * qx + qy * qy);
    const float tb0 = af[4], tb1 = af[5], tb2 = af[6];

    const int at = aatype[r];
    const float* mf = frames + (size_t)at * 128;

    float rf[8][3][3], tf[8][3];
#pragma unroll
    for (int g = 0; g < 8; g++) {
#pragma unroll
        for (int i = 0; i < 3; i++) {
            float m0 = mf[g * 16 + i * 4 + 0];
            float m1 = mf[g * 16 + i * 4 + 1];
            float m2 = mf[g * 16 + i * 4 + 2];
            float m3 = mf[g * 16 + i * 4 + 3];
            rf[g][i][0] = m0;
            rf[g][i][1] = m1 * cv[g] + m2 * sv[g];
            rf[g][i][2] = -m1 * sv[g] + m2 * cv[g];
            tf[g][i] = m3;
        }
    }

#pragma unroll
    for (int g = 5; g < 8; g++) {
        float R[3][3], T[3];
#pragma unroll
        for (int i = 0; i < 3; i++) {
#pragma unroll
            for (int j = 0; j < 3; j++)
                R[i][j] = rf[g - 1][i][0] * rf[g][0][j]
                        + rf[g - 1][i][1] * rf[g][1][j]
                        + rf[g - 1][i][2] * rf[g][2][j];
            T[i] = rf[g - 1][i][0] * tf[g][0]
                 + rf[g - 1][i][1] * tf[g][1]
                 + rf[g - 1][i][2] * tf[g][2] + tf[g - 1][i];
        }
#pragma unroll
        for (int i = 0; i < 3; i++) {
#pragma unroll
            for (int j = 0; j < 3; j++) rf[g][i][j] = R[i][j];
            tf[g][i] = T[i];
        }
    }

    int ga[14];
    float mk[14];
    float lp[14][3];
#pragma unroll
    for (int a = 0; a < 14; a++) {
        ga[a] = gidx[at * 14 + a];
        mk[a] = amask[at * 14 + a];
        lp[a][0] = lit[((size_t)at * 14 + a) * 3 + 0];
        lp[a][1] = lit[((size_t)at * 14 + a) * 3 + 1];
        lp[a][2] = lit[((size_t)at * 14 + a) * 3 + 2];
    }

    float pos[14][3];
#pragma unroll
    for (int a = 0; a < 14; a++) { pos[a][0] = 0.f; pos[a][1] = 0.f; pos[a][2] = 0.f; }

#pragma unroll
    for (int g = 0; g < 8; g++) {
        float R[3][3], T[3];
#pragma unroll
        for (int i = 0; i < 3; i++) {
#pragma unroll
            for (int j = 0; j < 3; j++)
                R[i][j] = rb[i][0] * rf[g][0][j] + rb[i][1] * rf[g][1][j] + rb[i][2] * rf[g][2][j];
        }
        T[0] = rb[0][0] * tf[g][0] + rb[0][1] * tf[g][1] + rb[0][2] * tf[g][2] + tb0;
        T[1] = rb[1][0] * tf[g][0] + rb[1][1] * tf[g][1] + rb[1][2] * tf[g][2] + tb1;
        T[2] = rb[2][0] * tf[g][0] + rb[2][1] * tf[g][1] + rb[2][2] * tf[g][2] + tb2;

#pragma unroll
        for (int i = 0; i < 3; i++) {
#pragma unroll
            for (int j = 0; j < 3; j++)
                out_rg[(size_t)r * 72 + g * 9 + i * 3 + j] = R[i][j];
            out_tg[(size_t)r * 24 + g * 3 + i] = T[i];
        }

#pragma unroll
        for (int a = 0; a < 14; a++) {
            if (ga[a] == g) {
                pos[a][0] = R[0][0] * lp[a][0] + R[0][1] * lp[a][1] + R[0][2] * lp[a][2] + T[0];
                pos[a][1] = R[1][0] * lp[a][0] + R[1][1] * lp[a][1] + R[1][2] * lp[a][2] + T[1];
                pos[a][2] = R[2][0] * lp[a][0] + R[2][1] * lp[a][1] + R[2][2] * lp[a][2] + T[2];
            }
        }
    }

#pragma unroll
    for (int a = 0; a < 14; a++) {
        out_pos[(size_t)r * 42 + a * 3 + 0] = pos[a][0] * mk[a];
        out_pos[(size_t)r * 42 + a * 3 + 1] = pos[a][1] * mk[a];
        out_pos[(size_t)r * 42 + a * 3 + 2] = pos[a][2] * mk[a];
    }
}

// ---------------------------------------------------------------------------
extern "C" void kernel_launch(void* const* d_in, const int* in_sizes, int n_in,
                              void* d_out, int out_size)
{
    const float* affine = (const float*)d_in[0];
    const float* rep0   = (const float*)d_in[1];
    const float* rep1   = (const float*)d_in[2];
    const int*   aatype = (const int*)d_in[3];
    const float* w_in0  = (const float*)d_in[4];
    const float* b_in0  = (const float*)d_in[5];
    const float* w_in1  = (const float*)d_in[6];
    const float* b_in1  = (const float*)d_in[7];
    const float* Wr1    = (const float*)d_in[8];
    const float* br1    = (const float*)d_in[9];
    const float* Wr2    = (const float*)d_in[10];
    const float* br2    = (const float*)d_in[11];
    const float* w_ang  = (const float*)d_in[12];
    const float* b_ang  = (const float*)d_in[13];
    const float* frames = (const float*)d_in[14];
    const int*   gidx   = (const int*)d_in[15];
    const float* amask  = (const float*)d_in[16];
    const float* lit    = (const float*)d_in[17];
    float* out = (float*)d_out;

    const int n = in_sizes[0] / 7;

    float* act = nullptr;
    cudaGetSymbolAddress((void**)&act, g_act);

    static bool attr_set = false;
    if (!attr_set) {
        cudaFuncSetAttribute(fused_mlp, cudaFuncAttributeMaxDynamicSharedMemorySize, SMEM_TOTAL);
        attr_set = true;
    }

    pack_weights<<<10, 256>>>(w_in0, w_in1, Wr1, Wr2);
    fused_mlp<<<n / 128, 256, SMEM_TOTAL>>>(rep0, rep1, b_in0, b_in1, br1, br2, act);
    epilogue_kernel<<<(n + 63) / 64, 64>>>(act, affine, aatype, w_ang, b_ang,
                                           frames, gidx, amask, lit, out, n);
}

// round 5
// speedup vs baseline: 2.7553x; 1.3312x over previous
#include <cuda_runtime.h>
#include <cuda_bf16.h>
#include <cstdint>
#include <cstddef>

#define N_MAX 131072

// Scratch (allocation-free rule: __device__ globals)
__device__ float g_act[(size_t)N_MAX * 128];
// 10 weight tiles x {hi,lo} x 16384 bf16, layout [n][k] (n-major), unpadded
__device__ __nv_bfloat16 g_wpk[10 * 2 * 16384];

// ---------------------------------------------------------------------------
// PTX helpers
// ---------------------------------------------------------------------------
__device__ __forceinline__ uint32_t smem_u32(const void* p) {
    uint32_t a;
    asm("{ .reg .u64 t; cvta.to.shared.u64 t, %1; cvt.u32.u64 %0, t; }" : "=r"(a) : "l"(p));
    return a;
}
__device__ __forceinline__ void ldsm_x4(uint32_t addr, uint32_t* r) {
    asm volatile("ldmatrix.sync.aligned.m8n8.x4.shared.b16 {%0,%1,%2,%3}, [%4];"
        : "=r"(r[0]), "=r"(r[1]), "=r"(r[2]), "=r"(r[3]) : "r"(addr));
}
__device__ __forceinline__ void mma16816(float* d, const uint32_t* a, uint32_t b0, uint32_t b1) {
    asm volatile(
        "mma.sync.aligned.m16n8k16.row.col.f32.bf16.bf16.f32 "
        "{%0,%1,%2,%3}, {%4,%5,%6,%7}, {%8,%9}, {%0,%1,%2,%3};"
        : "+f"(d[0]), "+f"(d[1]), "+f"(d[2]), "+f"(d[3])
        : "r"(a[0]), "r"(a[1]), "r"(a[2]), "r"(a[3]), "r"(b0), "r"(b1));
}
__device__ __forceinline__ uint32_t packbf(float a, float b) {
    __nv_bfloat162 h = __floats2bfloat162_rn(a, b);
    return *reinterpret_cast<uint32_t*>(&h);
}
__device__ __forceinline__ void cp_async16(uint32_t dst, const void* src) {
    asm volatile("cp.async.cg.shared.global [%0], [%1], 16;" :: "r"(dst), "l"(src));
}
#define CP_COMMIT() asm volatile("cp.async.commit_group;" ::: "memory")
#define CP_WAIT(N)  asm volatile("cp.async.wait_group %0;" :: "n"(N) : "memory")

// ---------------------------------------------------------------------------
// Weight pack: [k][n] fp32 -> [n][k] bf16 hi/lo split, output-coalesced.
// tile 0-2: w_in0 k-chunks; 3-5: w_in1; 6: Wr1[0]; 7: Wr2[0]; 8: Wr1[1]; 9: Wr2[1]
// grid = 80 (tile = bid/8, part = bid%8)
// ---------------------------------------------------------------------------
__global__ void pack_weights(const float* __restrict__ w_in0, const float* __restrict__ w_in1,
                             const float* __restrict__ Wr1, const float* __restrict__ Wr2)
{
    int tile = blockIdx.x >> 3;
    int part = blockIdx.x & 7;
    const float* W;
    if (tile < 3)       W = w_in0 + (size_t)tile * 16384;
    else if (tile < 6)  W = w_in1 + (size_t)(tile - 3) * 16384;
    else if (tile == 6) W = Wr1;
    else if (tile == 7) W = Wr2;
    else if (tile == 8) W = Wr1 + 16384;
    else                W = Wr2 + 16384;
    __nv_bfloat16* hi_out = g_wpk + (size_t)tile * 2 * 16384;
    __nv_bfloat16* lo_out = hi_out + 16384;
    // output index i = nn*128 + k : coalesced bf16 writes, strided reads (high MLP)
#pragma unroll
    for (int it = 0; it < 8; it++) {
        int i = part * 2048 + it * 256 + threadIdx.x;
        int nn = i >> 7, k = i & 127;
        float v = W[(size_t)k * 128 + nn];
        __nv_bfloat16 h = __float2bfloat16(v);
        hi_out[i] = h;
        lo_out[i] = __float2bfloat16(v - __bfloat162float(h));
    }
}

// ---------------------------------------------------------------------------
// Fused MLP on mma.sync bf16 (3-term split).  One 128-row tile per CTA,
// 256 threads (8 warps: 4m x 2n, 32x64 per warp).  B tiles double-buffered
// via cp.async; residual kept in registers (no fp32 stage buffer).
// ---------------------------------------------------------------------------
#define LDT        136                      // padded stride in bf16 elems
#define TILE_B     (128 * LDT * 2)          // 34816 bytes per tile
#define A_HI_OFF   0
#define A_LO_OFF   (TILE_B)
#define BBUF_OFF(s) ((2 + 2 * (s)) * TILE_B)   // each buf = hi tile + lo tile
#define SMEM_TOTAL (6 * TILE_B)             // 208896

__device__ __forceinline__ void gemm_k128(
    uint32_t aHi, uint32_t aLo, uint32_t bHi, uint32_t bLo,
    uint32_t aoff0, uint32_t aoff1, const uint32_t* boff,
    float acc[2][8][4])
{
#pragma unroll
    for (int ks = 0; ks < 8; ks++) {
        const uint32_t kb2 = ks * 32;  // 16 elems * 2 bytes
        uint32_t ah[2][4], al[2][4], bh[4][4], bl[4][4];
        ldsm_x4(aHi + aoff0 + kb2, ah[0]);
        ldsm_x4(aHi + aoff1 + kb2, ah[1]);
        ldsm_x4(aLo + aoff0 + kb2, al[0]);
        ldsm_x4(aLo + aoff1 + kb2, al[1]);
#pragma unroll
        for (int p = 0; p < 4; p++) {
            ldsm_x4(bHi + boff[p] + kb2, bh[p]);
            ldsm_x4(bLo + boff[p] + kb2, bl[p]);
        }
#pragma unroll
        for (int i = 0; i < 2; i++)
#pragma unroll
            for (int p = 0; p < 4; p++)
#pragma unroll
                for (int h = 0; h < 2; h++) {
                    float* d = acc[i][2 * p + h];
                    mma16816(d, ah[i], bh[p][2 * h], bh[p][2 * h + 1]);
                    mma16816(d, ah[i], bl[p][2 * h], bl[p][2 * h + 1]);
                    mma16816(d, al[i], bh[p][2 * h], bh[p][2 * h + 1]);
                }
    }
}

__global__ void __launch_bounds__(256, 1) fused_mlp(
    const float* __restrict__ rep0, const float* __restrict__ rep1,
    const float* __restrict__ b_in0, const float* __restrict__ b_in1,
    const float* __restrict__ br1, const float* __restrict__ br2,
    float* __restrict__ act_out)
{
    extern __shared__ char smem[];
    char* A_hi = smem + A_HI_OFF;
    char* A_lo = smem + A_LO_OFF;

    const int tid = threadIdx.x;
    const int wid = tid >> 5;
    const int lane = tid & 31;
    const int wm = wid & 3;        // 0..3 (m)
    const int wn = wid >> 2;       // 0..1 (n)
    const int row0 = blockIdx.x * 128;

    const uint32_t sb = smem_u32(smem);
    const uint32_t aHi = sb + A_HI_OFF;
    const uint32_t aLo = sb + A_LO_OFF;

    // per-thread ldmatrix byte offsets
    const uint32_t aoff0 = ((wm * 32 + (lane & 15)) * LDT + ((lane >> 4) << 3)) * 2;
    const uint32_t aoff1 = aoff0 + 16 * LDT * 2;
    uint32_t boff[4];
#pragma unroll
    for (int p = 0; p < 4; p++)
        boff[p] = ((wn * 64 + p * 16 + (lane & 7) + ((lane >> 4) << 3)) * LDT
                   + (((lane >> 3) & 1) << 3)) * 2;

    // epilogue per-thread coordinates
    const int ep_r0 = wm * 32 + (lane >> 2);      // + i*16, + half*8
    const int ep_c0 = wn * 64 + (lane & 3) * 2;   // + j*8

    float acc[2][8][4];
    float res[2][8][4];
#pragma unroll
    for (int i = 0; i < 2; i++)
#pragma unroll
        for (int j = 0; j < 8; j++)
#pragma unroll
            for (int q = 0; q < 4; q++) acc[i][j][q] = 0.f;

    // ---- B prefetch helper (lambda-free, inline) -------------------------
    // copies tile t into buffer s: hi 2048x16B + lo 2048x16B, padded rows
    auto issue_B = [&](int t, int s) {
        const char* src = (const char*)(g_wpk + (size_t)t * 2 * 16384);
        const uint32_t base = sb + BBUF_OFF(s);
#pragma unroll
        for (int it = 0; it < 16; it++) {
            int i = it * 256 + tid;
            int half = i >> 11;
            int j = i & 2047;
            int r = j >> 4, ch = j & 15;
            cp_async16(base + half * TILE_B + r * (LDT * 2) + ch * 16,
                       src + (size_t)i * 16);
        }
        CP_COMMIT();
    };

    issue_B(0, 0);

    // ============ 10 GEMM stages: g 0-5 input (K=768), g 6-9 resnet =======
    for (int g = 0; g < 10; g++) {
        const int buf = g & 1;

        if (g < 6) {
            // stage A chunk: relu + hi/lo split (overlaps pending cp.async)
            const float* src = (g < 3) ? rep0 : rep1;
            const int kb = (g % 3) * 128;
#pragma unroll
            for (int it = 0; it < 16; it++) {
                int i = it * 256 + tid;
                int r = i >> 5, c4 = (i & 31) * 4;
                float4 v = *(const float4*)(src + (size_t)(row0 + r) * 384 + kb + c4);
                v.x = fmaxf(v.x, 0.f); v.y = fmaxf(v.y, 0.f);
                v.z = fmaxf(v.z, 0.f); v.w = fmaxf(v.w, 0.f);
                __nv_bfloat16 h0 = __float2bfloat16(v.x), h1 = __float2bfloat16(v.y);
                __nv_bfloat16 h2 = __float2bfloat16(v.z), h3 = __float2bfloat16(v.w);
                uint32_t off = (r * LDT + c4) * 2;
                uint2 ph, pl;
                ph.x = packbf(__bfloat162float(h0), __bfloat162float(h1));
                ph.y = packbf(__bfloat162float(h2), __bfloat162float(h3));
                pl.x = packbf(v.x - __bfloat162float(h0), v.y - __bfloat162float(h1));
                pl.y = packbf(v.z - __bfloat162float(h2), v.w - __bfloat162float(h3));
                *(uint2*)(A_hi + off) = ph;
                *(uint2*)(A_lo + off) = pl;
            }
        }

        if (g + 1 < 10) { issue_B(g + 1, buf ^ 1); CP_WAIT(1); }
        else            { CP_WAIT(0); }
        __syncthreads();

        if (g >= 6) {
#pragma unroll
            for (int i = 0; i < 2; i++)
#pragma unroll
                for (int j = 0; j < 8; j++)
#pragma unroll
                    for (int q = 0; q < 4; q++) acc[i][j][q] = 0.f;
        }

        gemm_k128(aHi, aLo, sb + BBUF_OFF(buf), sb + BBUF_OFF(buf) + TILE_B,
                  aoff0, aoff1, boff, acc);
        __syncthreads();

        if (g == 5) {
            // input epilogue: res = acc + b_in0 + b_in1; relu-split -> A
#pragma unroll
            for (int i = 0; i < 2; i++)
#pragma unroll
                for (int j = 0; j < 8; j++) {
                    int c = ep_c0 + j * 8;
                    float bb0 = b_in0[c] + b_in1[c];
                    float bb1 = b_in0[c + 1] + b_in1[c + 1];
#pragma unroll
                    for (int half = 0; half < 2; half++) {
                        int r = ep_r0 + i * 16 + half * 8;
                        float x0 = acc[i][j][2 * half] + bb0;
                        float x1 = acc[i][j][2 * half + 1] + bb1;
                        res[i][j][2 * half] = x0;
                        res[i][j][2 * half + 1] = x1;
                        float p0 = fmaxf(x0, 0.f), p1 = fmaxf(x1, 0.f);
                        __nv_bfloat16 h0 = __float2bfloat16(p0), h1 = __float2bfloat16(p1);
                        *(uint32_t*)(A_hi + (r * LDT + c) * 2) =
                            packbf(__bfloat162float(h0), __bfloat162float(h1));
                        *(uint32_t*)(A_lo + (r * LDT + c) * 2) =
                            packbf(p0 - __bfloat162float(h0), p1 - __bfloat162float(h1));
                    }
                }
        } else if (g >= 6) {
            const int s = g - 6;
            const bool odd = (s & 1);
            const bool last = (s == 3);
            const float* bias = odd ? (br2 + (s >> 1) * 128) : (br1 + (s >> 1) * 128);
#pragma unroll
            for (int i = 0; i < 2; i++)
#pragma unroll
                for (int j = 0; j < 8; j++) {
                    int c = ep_c0 + j * 8;
                    float bb0 = bias[c], bb1 = bias[c + 1];
#pragma unroll
                    for (int half = 0; half < 2; half++) {
                        int r = ep_r0 + i * 16 + half * 8;
                        float x0 = acc[i][j][2 * half] + bb0;
                        float x1 = acc[i][j][2 * half + 1] + bb1;
                        if (odd) {
                            x0 += res[i][j][2 * half];
                            x1 += res[i][j][2 * half + 1];
                            res[i][j][2 * half] = x0;
                            res[i][j][2 * half + 1] = x1;
                        }
                        float p0 = fmaxf(x0, 0.f), p1 = fmaxf(x1, 0.f);
                        if (last) {
                            // final act: write relu(act) directly (epilogue uses relu only)
                            float2 w = make_float2(p0, p1);
                            *(float2*)(act_out + (size_t)(row0 + r) * 128 + c) = w;
                        } else {
                            __nv_bfloat16 h0 = __float2bfloat16(p0), h1 = __float2bfloat16(p1);
                            *(uint32_t*)(A_hi + (r * LDT + c) * 2) =
                                packbf(__bfloat162float(h0), __bfloat162float(h1));
                            *(uint32_t*)(A_lo + (r * LDT + c) * 2) =
                                packbf(p0 - __bfloat162float(h0), p1 - __bfloat162float(h1));
                        }
                    }
                }
        }
        // next iteration's pre-gemm __syncthreads orders the A rewrites
    }
}

// ---------------------------------------------------------------------------
// Per-residue geometry epilogue, spill-free restructure.
// 128 threads = 128 residues per block.  act arrives ALREADY relu'd.
// Dynamic smem: sW(1792) + sB(16) + sAct(128*129) floats; sAct reused as sRT.
// ---------------------------------------------------------------------------
#define EP_SW    0
#define EP_SB    1792
#define EP_ACT   1808
#define EP_FLOATS (1808 + 128 * 129)

__global__ void __launch_bounds__(128) epilogue_kernel(
    const float* __restrict__ act,
    const float* __restrict__ affine,
    const int* __restrict__ aatype,
    const float* __restrict__ w_ang,
    const float* __restrict__ b_ang,
    const float* __restrict__ frames,
    const int* __restrict__ gidx,
    const float* __restrict__ amask,
    const float* __restrict__ lit,
    float* __restrict__ out,
    int n)
{
    extern __shared__ float esh[];
    float* sW = esh + EP_SW;
    float* sB = esh + EP_SB;
    float* sAct = esh + EP_ACT;

    const int tid = threadIdx.x;
    const int r0 = blockIdx.x * 128;

#pragma unroll
    for (int it = 0; it < 14; it++) sW[it * 128 + tid] = w_ang[it * 128 + tid];
    if (tid < 14) sB[tid] = b_ang[tid];
    // act is already relu'd; float4 coalesced loads
#pragma unroll
    for (int it = 0; it < 32; it++) {
        int i = it * 128 + tid;
        int r = i >> 5, c4 = (i & 31) * 4;
        float4 v = *(const float4*)(act + (size_t)(r0 + r) * 128 + c4);
        sAct[r * 129 + c4 + 0] = v.x;
        sAct[r * 129 + c4 + 1] = v.y;
        sAct[r * 129 + c4 + 2] = v.z;
        sAct[r * 129 + c4 + 3] = v.w;
    }
    __syncthreads();

    const int r = r0 + tid;

    // --- unnorm = act_relu @ w_ang + b_ang ---
    float u[14];
#pragma unroll
    for (int j = 0; j < 14; j++) u[j] = sB[j];
    for (int k = 0; k < 128; k++) {
        float a = sAct[tid * 129 + k];
#pragma unroll
        for (int j = 0; j < 14; j++) u[j] += a * sW[k * 14 + j];
    }

    const size_t nsz = (size_t)n;
    float* out_ang = out;
    float* out_un  = out + nsz * 14;
    float* out_pos = out + nsz * 28;
    float* out_rg  = out + nsz * 70;
    float* out_tg  = out + nsz * 142;

    float sv[8], cv[8];
    sv[0] = 0.f; cv[0] = 1.f;
#pragma unroll
    for (int g = 0; g < 7; g++) {
        float s0 = u[2 * g], c0 = u[2 * g + 1];
        float inv = rsqrtf(fmaxf(s0 * s0 + c0 * c0, 1e-12f));
        float a0 = s0 * inv, a1 = c0 * inv;
        out_ang[(size_t)r * 14 + 2 * g]     = a0;
        out_ang[(size_t)r * 14 + 2 * g + 1] = a1;
        sv[g + 1] = a0;
        cv[g + 1] = a1;
    }
#pragma unroll
    for (int j = 0; j < 14; j++) out_un[(size_t)r * 14 + j] = u[j];

    // --- backbone rotation from quaternion ---
    const float* af = affine + (size_t)r * 7;
    float qw = af[0], qx = af[1], qy = af[2], qz = af[3];
    float qinv = rsqrtf(fmaxf(qw * qw + qx * qx + qy * qy + qz * qz, 1e-12f));
    qw *= qinv; qx *= qinv; qy *= qinv; qz *= qinv;
    float rb[9];
    rb[0] = 1.f - 2.f * (qy * qy + qz * qz);
    rb[1] = 2.f * (qx * qy - qw * qz);
    rb[2] = 2.f * (qx * qz + qw * qy);
    rb[3] = 2.f * (qx * qy + qw * qz);
    rb[4] = 1.f - 2.f * (qx * qx + qz * qz);
    rb[5] = 2.f * (qy * qz - qw * qx);
    rb[6] = 2.f * (qx * qz - qw * qy);
    rb[7] = 2.f * (qy * qz + qw * qx);
    rb[8] = 1.f - 2.f * (qx * qx + qy * qy);
    const float tb0 = af[4], tb1 = af[5], tb2 = af[6];

    const int at = aatype[r];
    const float* mf = frames + (size_t)at * 128;

    __syncthreads();                // everyone done with sAct -> reuse as sRT
    float* sRT = sAct;              // [res][stride 97]: 8 groups x 12 floats

    float prevR[9], prevT[3];
#pragma unroll
    for (int g = 0; g < 8; g++) {
        float rg[9], tg[3];
#pragma unroll
        for (int i = 0; i < 3; i++) {
            float m0 = mf[g * 16 + i * 4 + 0];
            float m1 = mf[g * 16 + i * 4 + 1];
            float m2 = mf[g * 16 + i * 4 + 2];
            float m3 = mf[g * 16 + i * 4 + 3];
            rg[i * 3 + 0] = m0;
            rg[i * 3 + 1] = m1 * cv[g] + m2 * sv[g];
            rg[i * 3 + 2] = -m1 * sv[g] + m2 * cv[g];
            tg[i] = m3;
        }
        if (g >= 5) {
            float R[9], T[3];
#pragma unroll
            for (int i = 0; i < 3; i++) {
#pragma unroll
                for (int j = 0; j < 3; j++)
                    R[i * 3 + j] = prevR[i * 3 + 0] * rg[j]
                                 + prevR[i * 3 + 1] * rg[3 + j]
                                 + prevR[i * 3 + 2] * rg[6 + j];
                T[i] = prevR[i * 3 + 0] * tg[0] + prevR[i * 3 + 1] * tg[1]
                     + prevR[i * 3 + 2] * tg[2] + prevT[i];
            }
#pragma unroll
            for (int i = 0; i < 9; i++) rg[i] = R[i];
#pragma unroll
            for (int i = 0; i < 3; i++) tg[i] = T[i];
        }
        if (g >= 4) {
#pragma unroll
            for (int i = 0; i < 9; i++) prevR[i] = rg[i];
#pragma unroll
            for (int i = 0; i < 3; i++) prevT[i] = tg[i];
        }
        // global frame: R = rb @ rg ; T = rb @ tg + tb
        float R[9], T[3];
#pragma unroll
        for (int i = 0; i < 3; i++) {
#pragma unroll
            for (int j = 0; j < 3; j++)
                R[i * 3 + j] = rb[i * 3 + 0] * rg[j] + rb[i * 3 + 1] * rg[3 + j]
                             + rb[i * 3 + 2] * rg[6 + j];
        }
        T[0] = rb[0] * tg[0] + rb[1] * tg[1] + rb[2] * tg[2] + tb0;
        T[1] = rb[3] * tg[0] + rb[4] * tg[1] + rb[5] * tg[2] + tb1;
        T[2] = rb[6] * tg[0] + rb[7] * tg[1] + rb[8] * tg[2] + tb2;

#pragma unroll
        for (int i = 0; i < 9; i++)
            out_rg[(size_t)r * 72 + g * 9 + i] = R[i];
#pragma unroll
        for (int i = 0; i < 3; i++)
            out_tg[(size_t)r * 24 + g * 3 + i] = T[i];

        float* rt = sRT + tid * 97 + g * 12;
#pragma unroll
        for (int i = 0; i < 9; i++) rt[i] = R[i];
#pragma unroll
        for (int i = 0; i < 3; i++) rt[9 + i] = T[i];
    }

    // --- atoms ---
#pragma unroll
    for (int a = 0; a < 14; a++) {
        int ga = gidx[at * 14 + a];
        float mk = amask[at * 14 + a];
        float l0 = lit[((size_t)at * 14 + a) * 3 + 0];
        float l1 = lit[((size_t)at * 14 + a) * 3 + 1];
        float l2 = lit[((size_t)at * 14 + a) * 3 + 2];
        const float* rt = sRT + tid * 97 + ga * 12;
        float p0 = (rt[0] * l0 + rt[1] * l1 + rt[2] * l2 + rt[9])  * mk;
        float p1 = (rt[3] * l0 + rt[4] * l1 + rt[5] * l2 + rt[10]) * mk;
        float p2 = (rt[6] * l0 + rt[7] * l1 + rt[8] * l2 + rt[11]) * mk;
        out_pos[(size_t)r * 42 + a * 3 + 0] = p0;
        out_pos[(size_t)r * 42 + a * 3 + 1] = p1;
        out_pos[(size_t)r * 42 + a * 3 + 2] = p2;
    }
}

// ---------------------------------------------------------------------------
extern "C" void kernel_launch(void* const* d_in, const int* in_sizes, int n_in,
                              void* d_out, int out_size)
{
    const float* affine = (const float*)d_in[0];
    const float* rep0   = (const float*)d_in[1];
    const float* rep1   = (const float*)d_in[2];
    const int*   aatype = (const int*)d_in[3];
    const float* w_in0  = (const float*)d_in[4];
    const float* b_in0  = (const float*)d_in[5];
    const float* w_in1  = (const float*)d_in[6];
    const float* b_in1  = (const float*)d_in[7];
    const float* Wr1    = (const float*)d_in[8];
    const float* br1    = (const float*)d_in[9];
    const float* Wr2    = (const float*)d_in[10];
    const float* br2    = (const float*)d_in[11];
    const float* w_ang  = (const float*)d_in[12];
    const float* b_ang  = (const float*)d_in[13];
    const float* frames = (const float*)d_in[14];
    const int*   gidx   = (const int*)d_in[15];
    const float* amask  = (const float*)d_in[16];
    const float* lit    = (const float*)d_in[17];
    float* out = (float*)d_out;

    const int n = in_sizes[0] / 7;

    float* act = nullptr;
    cudaGetSymbolAddress((void**)&act, g_act);

    static bool attr_set = false;
    if (!attr_set) {
        cudaFuncSetAttribute(fused_mlp, cudaFuncAttributeMaxDynamicSharedMemorySize, SMEM_TOTAL);
        cudaFuncSetAttribute(epilogue_kernel, cudaFuncAttributeMaxDynamicSharedMemorySize,
                             EP_FLOATS * 4);
        attr_set = true;
    }

    pack_weights<<<80, 256>>>(w_in0, w_in1, Wr1, Wr2);
    fused_mlp<<<n / 128, 256, SMEM_TOTAL>>>(rep0, rep1, b_in0, b_in1, br1, br2, act);
    epilogue_kernel<<<n / 128, 128, EP_FLOATS * 4>>>(act, affine, aatype, w_ang, b_ang,
                                                     frames, gidx, amask, lit, out, n);
}

// round 6
// speedup vs baseline: 2.8822x; 1.0460x over previous
#include <cuda_runtime.h>
#include <cuda_bf16.h>
#include <cstdint>
#include <cstddef>

// 11 weight tiles x {hi,lo} x 16384 bf16, layout [n][k] (n-major), unpadded.
// tiles 0-5: input GEMM k-chunks, 6-9: resnet, 10: w_ang padded to [16][128]
__device__ __nv_bfloat16 g_wpk[11 * 2 * 16384];

// ---------------------------------------------------------------------------
// PTX helpers
// ---------------------------------------------------------------------------
__device__ __forceinline__ uint32_t smem_u32(const void* p) {
    uint32_t a;
    asm("{ .reg .u64 t; cvta.to.shared.u64 t, %1; cvt.u32.u64 %0, t; }" : "=r"(a) : "l"(p));
    return a;
}
__device__ __forceinline__ void ldsm_x4(uint32_t addr, uint32_t* r) {
    asm volatile("ldmatrix.sync.aligned.m8n8.x4.shared.b16 {%0,%1,%2,%3}, [%4];"
        : "=r"(r[0]), "=r"(r[1]), "=r"(r[2]), "=r"(r[3]) : "r"(addr));
}
__device__ __forceinline__ void mma16816(float* d, const uint32_t* a, uint32_t b0, uint32_t b1) {
    asm volatile(
        "mma.sync.aligned.m16n8k16.row.col.f32.bf16.bf16.f32 "
        "{%0,%1,%2,%3}, {%4,%5,%6,%7}, {%8,%9}, {%0,%1,%2,%3};"
        : "+f"(d[0]), "+f"(d[1]), "+f"(d[2]), "+f"(d[3])
        : "r"(a[0]), "r"(a[1]), "r"(a[2]), "r"(a[3]), "r"(b0), "r"(b1));
}
__device__ __forceinline__ uint32_t packbf(float a, float b) {
    __nv_bfloat162 h = __floats2bfloat162_rn(a, b);
    return *reinterpret_cast<uint32_t*>(&h);
}
__device__ __forceinline__ void cp_async16(uint32_t dst, const void* src) {
    asm volatile("cp.async.cg.shared.global [%0], [%1], 16;" :: "r"(dst), "l"(src));
}
#define CP_COMMIT() asm volatile("cp.async.commit_group;" ::: "memory")
#define CP_WAIT(N)  asm volatile("cp.async.wait_group %0;" :: "n"(N) : "memory")

// ---------------------------------------------------------------------------
// Weight pack: [k][n] fp32 -> [n][k] bf16 hi/lo split, output-coalesced.
// grid = 81: blocks 0-79 handle tiles 0-9 (8 blocks each); block 80: w_ang.
// ---------------------------------------------------------------------------
__global__ void pack_weights(const float* __restrict__ w_in0, const float* __restrict__ w_in1,
                             const float* __restrict__ Wr1, const float* __restrict__ Wr2,
                             const float* __restrict__ w_ang)
{
    if (blockIdx.x == 80) {
        // w_ang [128k][14n] -> tile 10: [16n][128k], rows 14-15 zero
        __nv_bfloat16* hi_out = g_wpk + (size_t)10 * 2 * 16384;
        __nv_bfloat16* lo_out = hi_out + 16384;
#pragma unroll
        for (int it = 0; it < 8; it++) {
            int i = it * 256 + threadIdx.x;   // 0..2047
            int nn = i >> 7, k = i & 127;
            float v = (nn < 14) ? w_ang[k * 14 + nn] : 0.f;
            __nv_bfloat16 h = __float2bfloat16(v);
            hi_out[i] = h;
            lo_out[i] = __float2bfloat16(v - __bfloat162float(h));
        }
        return;
    }
    int tile = blockIdx.x >> 3;
    int part = blockIdx.x & 7;
    const float* W;
    if (tile < 3)       W = w_in0 + (size_t)tile * 16384;
    else if (tile < 6)  W = w_in1 + (size_t)(tile - 3) * 16384;
    else if (tile == 6) W = Wr1;
    else if (tile == 7) W = Wr2;
    else if (tile == 8) W = Wr1 + 16384;
    else                W = Wr2 + 16384;
    __nv_bfloat16* hi_out = g_wpk + (size_t)tile * 2 * 16384;
    __nv_bfloat16* lo_out = hi_out + 16384;
#pragma unroll
    for (int it = 0; it < 8; it++) {
        int i = part * 2048 + it * 256 + threadIdx.x;
        int nn = i >> 7, k = i & 127;
        float v = W[(size_t)k * 128 + nn];
        __nv_bfloat16 h = __float2bfloat16(v);
        hi_out[i] = h;
        lo_out[i] = __float2bfloat16(v - __bfloat162float(h));
    }
}

// ---------------------------------------------------------------------------
// Fully fused kernel: MLP (tensor) + angle GEMM (tensor) + geometry.
// One 128-row tile per CTA, 256 threads (8 warps: 4m x 2n).
// ---------------------------------------------------------------------------
#define LDT        136                      // padded stride in bf16 elems
#define TILE_B     (128 * LDT * 2)          // 34816 bytes per tile
#define A_HI_OFF   0
#define A_LO_OFF   (TILE_B)
#define BBUF_OFF(s) ((2 + 2 * (s)) * TILE_B)
#define SMEM_TOTAL (6 * TILE_B)             // 208896

__device__ __forceinline__ void gemm_k128(
    uint32_t aHi, uint32_t aLo, uint32_t bHi, uint32_t bLo,
    uint32_t aoff0, uint32_t aoff1, const uint32_t* boff,
    float acc[2][8][4])
{
#pragma unroll
    for (int ks = 0; ks < 8; ks++) {
        const uint32_t kb2 = ks * 32;
        uint32_t ah[2][4], al[2][4], bh[4][4], bl[4][4];
        ldsm_x4(aHi + aoff0 + kb2, ah[0]);
        ldsm_x4(aHi + aoff1 + kb2, ah[1]);
        ldsm_x4(aLo + aoff0 + kb2, al[0]);
        ldsm_x4(aLo + aoff1 + kb2, al[1]);
#pragma unroll
        for (int p = 0; p < 4; p++) {
            ldsm_x4(bHi + boff[p] + kb2, bh[p]);
            ldsm_x4(bLo + boff[p] + kb2, bl[p]);
        }
#pragma unroll
        for (int i = 0; i < 2; i++)
#pragma unroll
            for (int p = 0; p < 4; p++)
#pragma unroll
                for (int h = 0; h < 2; h++) {
                    float* d = acc[i][2 * p + h];
                    mma16816(d, ah[i], bh[p][2 * h], bh[p][2 * h + 1]);
                    mma16816(d, ah[i], bl[p][2 * h], bl[p][2 * h + 1]);
                    mma16816(d, al[i], bh[p][2 * h], bh[p][2 * h + 1]);
                }
    }
}

__global__ void __launch_bounds__(256, 1) fused_all(
    const float* __restrict__ rep0, const float* __restrict__ rep1,
    const float* __restrict__ b_in0, const float* __restrict__ b_in1,
    const float* __restrict__ br1, const float* __restrict__ br2,
    const float* __restrict__ b_ang,
    const float* __restrict__ affine,
    const int* __restrict__ aatype,
    const float* __restrict__ frames,
    const int* __restrict__ gidx,
    const float* __restrict__ amask,
    const float* __restrict__ lit,
    float* __restrict__ out, int n)
{
    extern __shared__ char smem[];
    char* A_hi = smem + A_HI_OFF;
    char* A_lo = smem + A_LO_OFF;

    const int tid = threadIdx.x;
    const int wid = tid >> 5;
    const int lane = tid & 31;
    const int wm = wid & 3;
    const int wn = wid >> 2;
    const int row0 = blockIdx.x * 128;

    const uint32_t sb = smem_u32(smem);
    const uint32_t aHi = sb + A_HI_OFF;
    const uint32_t aLo = sb + A_LO_OFF;

    const uint32_t aoff0 = ((wm * 32 + (lane & 15)) * LDT + ((lane >> 4) << 3)) * 2;
    const uint32_t aoff1 = aoff0 + 16 * LDT * 2;
    uint32_t boff[4];
#pragma unroll
    for (int p = 0; p < 4; p++)
        boff[p] = ((wn * 64 + p * 16 + (lane & 7) + ((lane >> 4) << 3)) * LDT
                   + (((lane >> 3) & 1) << 3)) * 2;

    const int ep_r0 = wm * 32 + (lane >> 2);
    const int ep_c0 = wn * 64 + (lane & 3) * 2;

    float acc[2][8][4];
    float res[2][8][4];
#pragma unroll
    for (int i = 0; i < 2; i++)
#pragma unroll
        for (int j = 0; j < 8; j++)
#pragma unroll
            for (int q = 0; q < 4; q++) acc[i][j][q] = 0.f;

    auto issue_B = [&](int t, int s) {
        const char* src = (const char*)(g_wpk + (size_t)t * 2 * 16384);
        const uint32_t base = sb + BBUF_OFF(s);
#pragma unroll
        for (int it = 0; it < 16; it++) {
            int i = it * 256 + tid;
            int half = i >> 11;
            int j = i & 2047;
            int r = j >> 4, ch = j & 15;
            cp_async16(base + half * TILE_B + r * (LDT * 2) + ch * 16,
                       src + (size_t)i * 16);
        }
        CP_COMMIT();
    };
    // small copy: w_ang tile (16 rows hi + 16 rows lo)
    auto issue_Bang = [&](int s) {
        const char* src = (const char*)(g_wpk + (size_t)10 * 2 * 16384);
        const uint32_t base = sb + BBUF_OFF(s);
        if (tid < 128) {
            int i = tid;                 // 0..127: hi rows
            int half = i >> 6;           // 0: hi, 1: lo
            int j = i & 63;
            int r = j >> 2, ch = j & 3;  // 16 rows x 4 chunks(64B) = 16x64... 
            // 16 rows * 128k * 2B = 4096 B per half => 256 x16B => rows 16, ch 16
            (void)r; (void)ch;
        }
        // simpler: 512 x 16B chunks total (2 halves x 16 rows x 16 chunks)
        {
            int i = tid;                 // need 512 iters over 256 threads: 2 per thread
#pragma unroll
            for (int it = 0; it < 2; it++) {
                int idx = it * 256 + i;          // 0..511
                int half = idx >> 8;             // 0 hi, 1 lo
                int j = idx & 255;               // 16 rows x 16 chunks
                int r = j >> 4, ch = j & 15;
                cp_async16(base + half * TILE_B + r * (LDT * 2) + ch * 16,
                           src + (size_t)half * 32768 + (size_t)(r * 128 * 2 + ch * 16));
            }
        }
        CP_COMMIT();
    };

    issue_B(0, 0);

    // ============ 10 GEMM stages: g 0-5 input (K=768), g 6-9 resnet =======
    for (int g = 0; g < 10; g++) {
        const int buf = g & 1;

        if (g < 6) {
            const float* src = (g < 3) ? rep0 : rep1;
            const int kb = (g % 3) * 128;
#pragma unroll
            for (int it = 0; it < 16; it++) {
                int i = it * 256 + tid;
                int r = i >> 5, c4 = (i & 31) * 4;
                float4 v = *(const float4*)(src + (size_t)(row0 + r) * 384 + kb + c4);
                v.x = fmaxf(v.x, 0.f); v.y = fmaxf(v.y, 0.f);
                v.z = fmaxf(v.z, 0.f); v.w = fmaxf(v.w, 0.f);
                __nv_bfloat16 h0 = __float2bfloat16(v.x), h1 = __float2bfloat16(v.y);
                __nv_bfloat16 h2 = __float2bfloat16(v.z), h3 = __float2bfloat16(v.w);
                uint32_t off = (r * LDT + c4) * 2;
                uint2 ph, pl;
                ph.x = packbf(__bfloat162float(h0), __bfloat162float(h1));
                ph.y = packbf(__bfloat162float(h2), __bfloat162float(h3));
                pl.x = packbf(v.x - __bfloat162float(h0), v.y - __bfloat162float(h1));
                pl.y = packbf(v.z - __bfloat162float(h2), v.w - __bfloat162float(h3));
                *(uint2*)(A_hi + off) = ph;
                *(uint2*)(A_lo + off) = pl;
            }
        }

        if (g + 1 < 10) { issue_B(g + 1, buf ^ 1); CP_WAIT(1); }
        else            { issue_Bang(buf ^ 1);     CP_WAIT(1); }
        __syncthreads();

        if (g >= 6) {
#pragma unroll
            for (int i = 0; i < 2; i++)
#pragma unroll
                for (int j = 0; j < 8; j++)
#pragma unroll
                    for (int q = 0; q < 4; q++) acc[i][j][q] = 0.f;
        }

        gemm_k128(aHi, aLo, sb + BBUF_OFF(buf), sb + BBUF_OFF(buf) + TILE_B,
                  aoff0, aoff1, boff, acc);
        __syncthreads();

        if (g == 5) {
#pragma unroll
            for (int i = 0; i < 2; i++)
#pragma unroll
                for (int j = 0; j < 8; j++) {
                    int c = ep_c0 + j * 8;
                    float bb0 = b_in0[c] + b_in1[c];
                    float bb1 = b_in0[c + 1] + b_in1[c + 1];
#pragma unroll
                    for (int half = 0; half < 2; half++) {
                        int r = ep_r0 + i * 16 + half * 8;
                        float x0 = acc[i][j][2 * half] + bb0;
                        float x1 = acc[i][j][2 * half + 1] + bb1;
                        res[i][j][2 * half] = x0;
                        res[i][j][2 * half + 1] = x1;
                        float p0 = fmaxf(x0, 0.f), p1 = fmaxf(x1, 0.f);
                        __nv_bfloat16 h0 = __float2bfloat16(p0), h1 = __float2bfloat16(p1);
                        *(uint32_t*)(A_hi + (r * LDT + c) * 2) =
                            packbf(__bfloat162float(h0), __bfloat162float(h1));
                        *(uint32_t*)(A_lo + (r * LDT + c) * 2) =
                            packbf(p0 - __bfloat162float(h0), p1 - __bfloat162float(h1));
                    }
                }
        } else if (g >= 6) {
            const int s = g - 6;
            const bool odd = (s & 1);
            const float* bias = odd ? (br2 + (s >> 1) * 128) : (br1 + (s >> 1) * 128);
#pragma unroll
            for (int i = 0; i < 2; i++)
#pragma unroll
                for (int j = 0; j < 8; j++) {
                    int c = ep_c0 + j * 8;
                    float bb0 = bias[c], bb1 = bias[c + 1];
#pragma unroll
                    for (int half = 0; half < 2; half++) {
                        int r = ep_r0 + i * 16 + half * 8;
                        float x0 = acc[i][j][2 * half] + bb0;
                        float x1 = acc[i][j][2 * half + 1] + bb1;
                        if (odd) {
                            x0 += res[i][j][2 * half];
                            x1 += res[i][j][2 * half + 1];
                            res[i][j][2 * half] = x0;
                            res[i][j][2 * half + 1] = x1;
                        }
                        float p0 = fmaxf(x0, 0.f), p1 = fmaxf(x1, 0.f);
                        __nv_bfloat16 h0 = __float2bfloat16(p0), h1 = __float2bfloat16(p1);
                        *(uint32_t*)(A_hi + (r * LDT + c) * 2) =
                            packbf(__bfloat162float(h0), __bfloat162float(h1));
                        *(uint32_t*)(A_lo + (r * LDT + c) * 2) =
                            packbf(p0 - __bfloat162float(h0), p1 - __bfloat162float(h1));
                    }
                }
        }
    }

    // ============ angle GEMM: unnorm = relu(act) @ w_ang + b_ang ==========
    // w_ang tile is in BBUF(0^...): after g=9 (buf=1), issue_Bang went to buf 0.
    CP_WAIT(0);
    __syncthreads();

    float* sU = (float*)(smem + BBUF_OFF(1));   // [128][15] unnorm staging

    if (wn == 0) {
        const uint32_t bHa = sb + BBUF_OFF(0);
        const uint32_t bLa = sb + BBUF_OFF(0) + TILE_B;
        float uacc[2][2][4];
#pragma unroll
        for (int i = 0; i < 2; i++)
#pragma unroll
            for (int h = 0; h < 2; h++)
#pragma unroll
                for (int q = 0; q < 4; q++) uacc[i][h][q] = 0.f;
#pragma unroll
        for (int ks = 0; ks < 8; ks++) {
            const uint32_t kb2 = ks * 32;
            uint32_t ah[2][4], al[2][4], bh[4], bl[4];
            ldsm_x4(aHi + aoff0 + kb2, ah[0]);
            ldsm_x4(aHi + aoff1 + kb2, ah[1]);
            ldsm_x4(aLo + aoff0 + kb2, al[0]);
            ldsm_x4(aLo + aoff1 + kb2, al[1]);
            ldsm_x4(bHa + boff[0] + kb2, bh);
            ldsm_x4(bLa + boff[0] + kb2, bl);
#pragma unroll
            for (int i = 0; i < 2; i++)
#pragma unroll
                for (int h = 0; h < 2; h++) {
                    float* d = uacc[i][h];
                    mma16816(d, ah[i], bh[2 * h], bh[2 * h + 1]);
                    mma16816(d, ah[i], bl[2 * h], bl[2 * h + 1]);
                    mma16816(d, al[i], bh[2 * h], bh[2 * h + 1]);
                }
        }
        // scatter unnorm (+bias) to sU
#pragma unroll
        for (int i = 0; i < 2; i++)
#pragma unroll
            for (int h = 0; h < 2; h++) {
                int c = (lane & 3) * 2 + h * 8;
                if (c < 14) {
                    float bb0 = b_ang[c], bb1 = b_ang[c + 1];
#pragma unroll
                    for (int half = 0; half < 2; half++) {
                        int r = ep_r0 + i * 16 + half * 8;
                        sU[r * 15 + c]     = uacc[i][h][2 * half] + bb0;
                        sU[r * 15 + c + 1] = uacc[i][h][2 * half + 1] + bb1;
                    }
                }
            }
    }
    __syncthreads();

    // ============ per-residue geometry (threads 0-127) ====================
    if (tid >= 128) return;
    const int r = row0 + tid;

    float u[14];
#pragma unroll
    for (int j = 0; j < 14; j++) u[j] = sU[tid * 15 + j];

    const size_t nsz = (size_t)n;
    float* out_ang = out;
    float* out_un  = out + nsz * 14;
    float* out_pos = out + nsz * 28;
    float* out_rg  = out + nsz * 70;
    float* out_tg  = out + nsz * 142;

    float sv[8], cv[8];
    sv[0] = 0.f; cv[0] = 1.f;
#pragma unroll
    for (int g = 0; g < 7; g++) {
        float s0 = u[2 * g], c0 = u[2 * g + 1];
        float inv = rsqrtf(fmaxf(s0 * s0 + c0 * c0, 1e-12f));
        float a0 = s0 * inv, a1 = c0 * inv;
        out_ang[(size_t)r * 14 + 2 * g]     = a0;
        out_ang[(size_t)r * 14 + 2 * g + 1] = a1;
        sv[g + 1] = a0;
        cv[g + 1] = a1;
    }
#pragma unroll
    for (int j = 0; j < 14; j++) out_un[(size_t)r * 14 + j] = u[j];

    const float* af = affine + (size_t)r * 7;
    float qw = af[0], qx = af[1], qy = af[2], qz = af[3];
    float qinv = rsqrtf(fmaxf(qw * qw + qx * qx + qy * qy + qz * qz, 1e-12f));
    qw *= qinv; qx *= qinv; qy *= qinv; qz *= qinv;
    float rb[9];
    rb[0] = 1.f - 2.f * (qy * qy + qz * qz);
    rb[1] = 2.f * (qx * qy - qw * qz);
    rb[2] = 2.f * (qx * qz + qw * qy);
    rb[3] = 2.f * (qx * qy + qw * qz);
    rb[4] = 1.f - 2.f * (qx * qx + qz * qz);
    rb[5] = 2.f * (qy * qz - qw * qx);
    rb[6] = 2.f * (qx * qz - qw * qy);
    rb[7] = 2.f * (qy * qz + qw * qx);
    rb[8] = 1.f - 2.f * (qx * qx + qy * qy);
    const float tb0 = af[4], tb1 = af[5], tb2 = af[6];

    const int at = aatype[r];
    const float* mf = frames + (size_t)at * 128;

    float* sRT = (float*)(smem + A_HI_OFF);   // A tiles dead; [res][97]

    float prevR[9], prevT[3];
#pragma unroll
    for (int g = 0; g < 8; g++) {
        float rg[9], tg[3];
#pragma unroll
        for (int i = 0; i < 3; i++) {
            float m0 = mf[g * 16 + i * 4 + 0];
            float m1 = mf[g * 16 + i * 4 + 1];
            float m2 = mf[g * 16 + i * 4 + 2];
            float m3 = mf[g * 16 + i * 4 + 3];
            rg[i * 3 + 0] = m0;
            rg[i * 3 + 1] = m1 * cv[g] + m2 * sv[g];
            rg[i * 3 + 2] = -m1 * sv[g] + m2 * cv[g];
            tg[i] = m3;
        }
        if (g >= 5) {
            float R[9], T[3];
#pragma unroll
            for (int i = 0; i < 3; i++) {
#pragma unroll
                for (int j = 0; j < 3; j++)
                    R[i * 3 + j] = prevR[i * 3 + 0] * rg[j]
                                 + prevR[i * 3 + 1] * rg[3 + j]
                                 + prevR[i * 3 + 2] * rg[6 + j];
                T[i] = prevR[i * 3 + 0] * tg[0] + prevR[i * 3 + 1] * tg[1]
                     + prevR[i * 3 + 2] * tg[2] + prevT[i];
            }
#pragma unroll
            for (int i = 0; i < 9; i++) rg[i] = R[i];
#pragma unroll
            for (int i = 0; i < 3; i++) tg[i] = T[i];
        }
        if (g >= 4) {
#pragma unroll
            for (int i = 0; i < 9; i++) prevR[i] = rg[i];
#pragma unroll
            for (int i = 0; i < 3; i++) prevT[i] = tg[i];
        }
        float R[9], T[3];
#pragma unroll
        for (int i = 0; i < 3; i++) {
#pragma unroll
            for (int j = 0; j < 3; j++)
                R[i * 3 + j] = rb[i * 3 + 0] * rg[j] + rb[i * 3 + 1] * rg[3 + j]
                             + rb[i * 3 + 2] * rg[6 + j];
        }
        T[0] = rb[0] * tg[0] + rb[1] * tg[1] + rb[2] * tg[2] + tb0;
        T[1] = rb[3] * tg[0] + rb[4] * tg[1] + rb[5] * tg[2] + tb1;
        T[2] = rb[6] * tg[0] + rb[7] * tg[1] + rb[8] * tg[2] + tb2;

#pragma unroll
        for (int i = 0; i < 9; i++)
            out_rg[(size_t)r * 72 + g * 9 + i] = R[i];
#pragma unroll
        for (int i = 0; i < 3; i++)
            out_tg[(size_t)r * 24 + g * 3 + i] = T[i];

        float* rt = sRT + tid * 97 + g * 12;
#pragma unroll
        for (int i = 0; i < 9; i++) rt[i] = R[i];
#pragma unroll
        for (int i = 0; i < 3; i++) rt[9 + i] = T[i];
    }

#pragma unroll
    for (int a = 0; a < 14; a++) {
        int ga = gidx[at * 14 + a];
        float mk = amask[at * 14 + a];
        float l0 = lit[((size_t)at * 14 + a) * 3 + 0];
        float l1 = lit[((size_t)at * 14 + a) * 3 + 1];
        float l2 = lit[((size_t)at * 14 + a) * 3 + 2];
        const float* rt = sRT + tid * 97 + ga * 12;
        float p0 = (rt[0] * l0 + rt[1] * l1 + rt[2] * l2 + rt[9])  * mk;
        float p1 = (rt[3] * l0 + rt[4] * l1 + rt[5] * l2 + rt[10]) * mk;
        float p2 = (rt[6] * l0 + rt[7] * l1 + rt[8] * l2 + rt[11]) * mk;
        out_pos[(size_t)r * 42 + a * 3 + 0] = p0;
        out_pos[(size_t)r * 42 + a * 3 + 1] = p1;
        out_pos[(size_t)r * 42 + a * 3 + 2] = p2;
    }
}

// ---------------------------------------------------------------------------
extern "C" void kernel_launch(void* const* d_in, const int* in_sizes, int n_in,
                              void* d_out, int out_size)
{
    const float* affine = (const float*)d_in[0];
    const float* rep0   = (const float*)d_in[1];
    const float* rep1   = (const float*)d_in[2];
    const int*   aatype = (const int*)d_in[3];
    const float* w_in0  = (const float*)d_in[4];
    const float* b_in0  = (const float*)d_in[5];
    const float* w_in1  = (const float*)d_in[6];
    const float* b_in1  = (const float*)d_in[7];
    const float* Wr1    = (const float*)d_in[8];
    const float* br1    = (const float*)d_in[9];
    const float* Wr2    = (const float*)d_in[10];
    const float* br2    = (const float*)d_in[11];
    const float* w_ang  = (const float*)d_in[12];
    const float* b_ang  = (const float*)d_in[13];
    const float* frames = (const float*)d_in[14];
    const int*   gidx   = (const int*)d_in[15];
    const float* amask  = (const float*)d_in[16];
    const float* lit    = (const float*)d_in[17];
    float* out = (float*)d_out;

    const int n = in_sizes[0] / 7;

    static bool attr_set = false;
    if (!attr_set) {
        cudaFuncSetAttribute(fused_all, cudaFuncAttributeMaxDynamicSharedMemorySize, SMEM_TOTAL);
        attr_set = true;
    }

    pack_weights<<<81, 256>>>(w_in0, w_in1, Wr1, Wr2, w_ang);
    fused_all<<<n / 128, 256, SMEM_TOTAL>>>(rep0, rep1, b_in0, b_in1, br1, br2, b_ang,
                                            affine, aatype, frames, gidx, amask, lit,
                                            out, n);
}

// round 7
// speedup vs baseline: 3.0967x; 1.0744x over previous
#include <cuda_runtime.h>
#include <cuda_bf16.h>
#include <cstdint>
#include <cstddef>

// 11 weight tiles x {hi,lo} x 16384 bf16, layout [n][k] (n-major), unpadded.
// tiles 0-5: input GEMM k-chunks, 6-9: resnet, 10: w_ang padded to [16][128]
__device__ __nv_bfloat16 g_wpk[11 * 2 * 16384];

// ---------------------------------------------------------------------------
// PTX helpers
// ---------------------------------------------------------------------------
__device__ __forceinline__ uint32_t smem_u32(const void* p) {
    uint32_t a;
    asm("{ .reg .u64 t; cvta.to.shared.u64 t, %1; cvt.u32.u64 %0, t; }" : "=r"(a) : "l"(p));
    return a;
}
__device__ __forceinline__ void ldsm_x4(uint32_t addr, uint32_t* r) {
    asm volatile("ldmatrix.sync.aligned.m8n8.x4.shared.b16 {%0,%1,%2,%3}, [%4];"
        : "=r"(r[0]), "=r"(r[1]), "=r"(r[2]), "=r"(r[3]) : "r"(addr));
}
__device__ __forceinline__ void mma16816(float* d, const uint32_t* a, uint32_t b0, uint32_t b1) {
    asm volatile(
        "mma.sync.aligned.m16n8k16.row.col.f32.bf16.bf16.f32 "
        "{%0,%1,%2,%3}, {%4,%5,%6,%7}, {%8,%9}, {%0,%1,%2,%3};"
        : "+f"(d[0]), "+f"(d[1]), "+f"(d[2]), "+f"(d[3])
        : "r"(a[0]), "r"(a[1]), "r"(a[2]), "r"(a[3]), "r"(b0), "r"(b1));
}
__device__ __forceinline__ uint32_t packbf(float a, float b) {
    __nv_bfloat162 h = __floats2bfloat162_rn(a, b);
    return *reinterpret_cast<uint32_t*>(&h);
}
__device__ __forceinline__ void cp_async16(uint32_t dst, const void* src) {
    asm volatile("cp.async.cg.shared.global [%0], [%1], 16;" :: "r"(dst), "l"(src));
}
#define CP_COMMIT() asm volatile("cp.async.commit_group;" ::: "memory")
#define CP_WAIT(N)  asm volatile("cp.async.wait_group %0;" :: "n"(N) : "memory")

// ---------------------------------------------------------------------------
// Weight pack (unchanged): [k][n] fp32 -> [n][k] bf16 hi/lo split.
// grid = 81: blocks 0-79 tiles 0-9 (8 blocks each); block 80: w_ang tile 10.
// ---------------------------------------------------------------------------
__global__ void pack_weights(const float* __restrict__ w_in0, const float* __restrict__ w_in1,
                             const float* __restrict__ Wr1, const float* __restrict__ Wr2,
                             const float* __restrict__ w_ang)
{
    if (blockIdx.x == 80) {
        __nv_bfloat16* hi_out = g_wpk + (size_t)10 * 2 * 16384;
        __nv_bfloat16* lo_out = hi_out + 16384;
#pragma unroll
        for (int it = 0; it < 8; it++) {
            int i = it * 256 + threadIdx.x;
            int nn = i >> 7, k = i & 127;
            float v = (nn < 14) ? w_ang[k * 14 + nn] : 0.f;
            __nv_bfloat16 h = __float2bfloat16(v);
            hi_out[i] = h;
            lo_out[i] = __float2bfloat16(v - __bfloat162float(h));
        }
        return;
    }
    int tile = blockIdx.x >> 3;
    int part = blockIdx.x & 7;
    const float* W;
    if (tile < 3)       W = w_in0 + (size_t)tile * 16384;
    else if (tile < 6)  W = w_in1 + (size_t)(tile - 3) * 16384;
    else if (tile == 6) W = Wr1;
    else if (tile == 7) W = Wr2;
    else if (tile == 8) W = Wr1 + 16384;
    else                W = Wr2 + 16384;
    __nv_bfloat16* hi_out = g_wpk + (size_t)tile * 2 * 16384;
    __nv_bfloat16* lo_out = hi_out + 16384;
#pragma unroll
    for (int it = 0; it < 8; it++) {
        int i = part * 2048 + it * 256 + threadIdx.x;
        int nn = i >> 7, k = i & 127;
        float v = W[(size_t)k * 128 + nn];
        __nv_bfloat16 h = __float2bfloat16(v);
        hi_out[i] = h;
        lo_out[i] = __float2bfloat16(v - __bfloat162float(h));
    }
}

// ---------------------------------------------------------------------------
// Fully fused kernel, M=64 rows per CTA for 2 CTAs/SM residency.
// 256 threads, 8 warps: 4m x 2n, warp tile 16x64.
// SMEM: A hi/lo (64x136 bf16 each) + B hi/lo single buffer (128x136 each).
// ---------------------------------------------------------------------------
#define LDT        136
#define A_TILE_B   (64 * LDT * 2)           // 17408
#define B_TILE_B   (128 * LDT * 2)          // 34816
#define A_HI_OFF   0
#define A_LO_OFF   (A_TILE_B)
#define B_HI_OFF   (2 * A_TILE_B)           // 34816
#define B_LO_OFF   (B_HI_OFF + B_TILE_B)    // 69632
#define SU_OFF     (B_HI_OFF + 8192)        // inside B_HI, beyond w_ang rows
#define SMEM_TOTAL (B_LO_OFF + B_TILE_B)    // 104448

__global__ void __launch_bounds__(256, 2) fused_all(
    const float* __restrict__ rep0, const float* __restrict__ rep1,
    const float* __restrict__ b_in0, const float* __restrict__ b_in1,
    const float* __restrict__ br1, const float* __restrict__ br2,
    const float* __restrict__ b_ang,
    const float* __restrict__ affine,
    const int* __restrict__ aatype,
    const float* __restrict__ frames,
    const int* __restrict__ gidx,
    const float* __restrict__ amask,
    const float* __restrict__ lit,
    float* __restrict__ out, int n)
{
    extern __shared__ char smem[];
    char* A_hi = smem + A_HI_OFF;
    char* A_lo = smem + A_LO_OFF;

    const int tid = threadIdx.x;
    const int wid = tid >> 5;
    const int lane = tid & 31;
    const int wm = wid & 3;          // 0..3
    const int wn = wid >> 2;         // 0..1
    const int row0 = blockIdx.x * 64;

    const uint32_t sb = smem_u32(smem);
    const uint32_t aHi = sb + A_HI_OFF;
    const uint32_t aLo = sb + A_LO_OFF;
    const uint32_t bHi = sb + B_HI_OFF;
    const uint32_t bLo = sb + B_LO_OFF;

    // ldmatrix offsets: A m16k16 fragment per warp (rows wm*16..+15)
    const uint32_t aoff = ((wm * 16 + (lane & 15)) * LDT + ((lane >> 4) << 3)) * 2;
    uint32_t boff[4];
#pragma unroll
    for (int p = 0; p < 4; p++)
        boff[p] = ((wn * 64 + p * 16 + (lane & 7) + ((lane >> 4) << 3)) * LDT
                   + (((lane >> 3) & 1) << 3)) * 2;

    const int ep_r0 = wm * 16 + (lane >> 2);      // + half*8
    const int ep_c0 = wn * 64 + (lane & 3) * 2;   // + j*8

    float acc[8][4];
    float res[8][4];
#pragma unroll
    for (int j = 0; j < 8; j++)
#pragma unroll
        for (int q = 0; q < 4; q++) acc[j][q] = 0.f;

    auto issue_B = [&](int t) {
        const char* src = (const char*)(g_wpk + (size_t)t * 2 * 16384);
#pragma unroll
        for (int it = 0; it < 16; it++) {
            int i = it * 256 + tid;          // 0..4095
            int half = i >> 11;
            int j = i & 2047;
            int r = j >> 4, ch = j & 15;
            cp_async16(sb + B_HI_OFF + half * B_TILE_B + r * (LDT * 2) + ch * 16,
                       src + (size_t)half * 32768 + (size_t)j * 16);
        }
        CP_COMMIT();
    };

    // deferred epilogue of stage s (5..9): reads acc, updates res, writes A
    auto epilogue = [&](int s) {
#pragma unroll
        for (int j = 0; j < 8; j++) {
            int c = ep_c0 + j * 8;
            float bb0, bb1;
            if (s == 5)      { bb0 = b_in0[c] + b_in1[c]; bb1 = b_in0[c + 1] + b_in1[c + 1]; }
            else if ((s - 6) & 1) { bb0 = br2[((s - 6) >> 1) * 128 + c]; bb1 = br2[((s - 6) >> 1) * 128 + c + 1]; }
            else             { bb0 = br1[((s - 6) >> 1) * 128 + c]; bb1 = br1[((s - 6) >> 1) * 128 + c + 1]; }
            const bool keep = (s == 5) || (((s - 6) & 1) != 0);
#pragma unroll
            for (int half = 0; half < 2; half++) {
                int r = ep_r0 + half * 8;
                float x0 = acc[j][2 * half] + bb0;
                float x1 = acc[j][2 * half + 1] + bb1;
                if (s >= 6 && ((s - 6) & 1)) {
                    x0 += res[j][2 * half];
                    x1 += res[j][2 * half + 1];
                }
                if (keep) {
                    res[j][2 * half] = x0;
                    res[j][2 * half + 1] = x1;
                }
                float p0 = fmaxf(x0, 0.f), p1 = fmaxf(x1, 0.f);
                __nv_bfloat16 h0 = __float2bfloat16(p0), h1 = __float2bfloat16(p1);
                *(uint32_t*)(A_hi + (r * LDT + c) * 2) =
                    packbf(__bfloat162float(h0), __bfloat162float(h1));
                *(uint32_t*)(A_lo + (r * LDT + c) * 2) =
                    packbf(p0 - __bfloat162float(h0), p1 - __bfloat162float(h1));
            }
        }
    };

    // ============ 10 GEMM stages: g 0-5 input (K=768), g 6-9 resnet =======
    for (int g = 0; g < 10; g++) {
        issue_B(g);

        if (g < 6) {
            // stage A chunk: relu + hi/lo split (overlaps B cp.async)
            const float* src = (g < 3) ? rep0 : rep1;
            const int kb = (g % 3) * 128;
#pragma unroll
            for (int it = 0; it < 8; it++) {
                int i = it * 256 + tid;          // 0..2047
                int r = i >> 5, c4 = (i & 31) * 4;
                float4 v = *(const float4*)(src + (size_t)(row0 + r) * 384 + kb + c4);
                v.x = fmaxf(v.x, 0.f); v.y = fmaxf(v.y, 0.f);
                v.z = fmaxf(v.z, 0.f); v.w = fmaxf(v.w, 0.f);
                __nv_bfloat16 h0 = __float2bfloat16(v.x), h1 = __float2bfloat16(v.y);
                __nv_bfloat16 h2 = __float2bfloat16(v.z), h3 = __float2bfloat16(v.w);
                uint32_t off = (r * LDT + c4) * 2;
                uint2 ph, pl;
                ph.x = packbf(__bfloat162float(h0), __bfloat162float(h1));
                ph.y = packbf(__bfloat162float(h2), __bfloat162float(h3));
                pl.x = packbf(v.x - __bfloat162float(h0), v.y - __bfloat162float(h1));
                pl.y = packbf(v.z - __bfloat162float(h2), v.w - __bfloat162float(h3));
                *(uint2*)(A_hi + off) = ph;
                *(uint2*)(A_lo + off) = pl;
            }
        } else {
            // deferred epilogue of previous stage overlaps B cp.async
            epilogue(g - 1);
#pragma unroll
            for (int j = 0; j < 8; j++)
#pragma unroll
                for (int q = 0; q < 4; q++) acc[j][q] = 0.f;
        }

        CP_WAIT(0);
        __syncthreads();

        // GEMM K=128, 3-term bf16 split
#pragma unroll
        for (int ks = 0; ks < 8; ks++) {
            const uint32_t kb2 = ks * 32;
            uint32_t ah[4], al[4], bh[4][4], bl[4][4];
            ldsm_x4(aHi + aoff + kb2, ah);
            ldsm_x4(aLo + aoff + kb2, al);
#pragma unroll
            for (int p = 0; p < 4; p++) {
                ldsm_x4(bHi + boff[p] + kb2, bh[p]);
                ldsm_x4(bLo + boff[p] + kb2, bl[p]);
            }
#pragma unroll
            for (int p = 0; p < 4; p++)
#pragma unroll
                for (int h = 0; h < 2; h++) {
                    float* d = acc[2 * p + h];
                    mma16816(d, ah, bh[p][2 * h], bh[p][2 * h + 1]);
                    mma16816(d, ah, bl[p][2 * h], bl[p][2 * h + 1]);
                    mma16816(d, al, bh[p][2 * h], bh[p][2 * h + 1]);
                }
        }
        __syncthreads();
    }

    // ============ angle GEMM ==============================================
    // load w_ang tile into B (prior gemm done, post-gemm sync passed)
    {
        const char* src = (const char*)(g_wpk + (size_t)10 * 2 * 16384);
#pragma unroll
        for (int it = 0; it < 2; it++) {
            int idx = it * 256 + tid;        // 0..511
            int half = idx >> 8;
            int j = idx & 255;               // 16 rows x 16 chunks
            int r = j >> 4, ch = j & 15;
            cp_async16(sb + B_HI_OFF + half * B_TILE_B + r * (LDT * 2) + ch * 16,
                       src + (size_t)half * 32768 + (size_t)j * 16);
        }
        CP_COMMIT();
    }
    epilogue(9);            // writes relu-split act into A (overlaps cp.async)
    CP_WAIT(0);
    __syncthreads();

    float* sU = (float*)(smem + SU_OFF);     // [64][15]

    if (wn == 0) {
        float uacc[2][4];
#pragma unroll
        for (int h = 0; h < 2; h++)
#pragma unroll
            for (int q = 0; q < 4; q++) uacc[h][q] = 0.f;
#pragma unroll
        for (int ks = 0; ks < 8; ks++) {
            const uint32_t kb2 = ks * 32;
            uint32_t ah[4], al[4], bh[4], bl[4];
            ldsm_x4(aHi + aoff + kb2, ah);
            ldsm_x4(aLo + aoff + kb2, al);
            ldsm_x4(bHi + boff[0] + kb2, bh);
            ldsm_x4(bLo + boff[0] + kb2, bl);
#pragma unroll
            for (int h = 0; h < 2; h++) {
                float* d = uacc[h];
                mma16816(d, ah, bh[2 * h], bh[2 * h + 1]);
                mma16816(d, ah, bl[2 * h], bl[2 * h + 1]);
                mma16816(d, al, bh[2 * h], bh[2 * h + 1]);
            }
        }
#pragma unroll
        for (int h = 0; h < 2; h++) {
            int c = (lane & 3) * 2 + h * 8;
            if (c < 14) {
                float bb0 = b_ang[c], bb1 = b_ang[c + 1];
#pragma unroll
                for (int half = 0; half < 2; half++) {
                    int r = ep_r0 + half * 8;
                    sU[r * 15 + c]     = uacc[h][2 * half] + bb0;
                    sU[r * 15 + c + 1] = uacc[h][2 * half + 1] + bb1;
                }
            }
        }
    }
    __syncthreads();

    // ============ per-residue geometry (threads 0-63) =====================
    if (tid >= 64) return;
    const int r = row0 + tid;

    float u[14];
#pragma unroll
    for (int j = 0; j < 14; j++) u[j] = sU[tid * 15 + j];

    const size_t nsz = (size_t)n;
    float* out_ang = out;
    float* out_un  = out + nsz * 14;
    float* out_pos = out + nsz * 28;
    float* out_rg  = out + nsz * 70;
    float* out_tg  = out + nsz * 142;

    float sv[8], cv[8];
    sv[0] = 0.f; cv[0] = 1.f;
#pragma unroll
    for (int g = 0; g < 7; g++) {
        float s0 = u[2 * g], c0 = u[2 * g + 1];
        float inv = rsqrtf(fmaxf(s0 * s0 + c0 * c0, 1e-12f));
        float a0 = s0 * inv, a1 = c0 * inv;
        out_ang[(size_t)r * 14 + 2 * g]     = a0;
        out_ang[(size_t)r * 14 + 2 * g + 1] = a1;
        sv[g + 1] = a0;
        cv[g + 1] = a1;
    }
#pragma unroll
    for (int j = 0; j < 14; j++) out_un[(size_t)r * 14 + j] = u[j];

    const float* af = affine + (size_t)r * 7;
    float qw = af[0], qx = af[1], qy = af[2], qz = af[3];
    float qinv = rsqrtf(fmaxf(qw * qw + qx * qx + qy * qy + qz * qz, 1e-12f));
    qw *= qinv; qx *= qinv; qy *= qinv; qz *= qinv;
    float rb[9];
    rb[0] = 1.f - 2.f * (qy * qy + qz * qz);
    rb[1] = 2.f * (qx * qy - qw * qz);
    rb[2] = 2.f * (qx * qz + qw * qy);
    rb[3] = 2.f * (qx * qy + qw * qz);
    rb[4] = 1.f - 2.f * (qx * qx + qz * qz);
    rb[5] = 2.f * (qy * qz - qw * qx);
    rb[6] = 2.f * (qx * qz - qw * qy);
    rb[7] = 2.f * (qy * qz + qw * qx);
    rb[8] = 1.f - 2.f * (qx * qx + qy * qy);
    const float tb0 = af[4], tb1 = af[5], tb2 = af[6];

    const int at = aatype[r];
    const float* mf = frames + (size_t)at * 128;

    float* sRT = (float*)(smem + A_HI_OFF);   // A dead; [64][97]

    float prevR[9], prevT[3];
#pragma unroll
    for (int g = 0; g < 8; g++) {
        float rg[9], tg[3];
#pragma unroll
        for (int i = 0; i < 3; i++) {
            float m0 = mf[g * 16 + i * 4 + 0];
            float m1 = mf[g * 16 + i * 4 + 1];
            float m2 = mf[g * 16 + i * 4 + 2];
            float m3 = mf[g * 16 + i * 4 + 3];
            rg[i * 3 + 0] = m0;
            rg[i * 3 + 1] = m1 * cv[g] + m2 * sv[g];
            rg[i * 3 + 2] = -m1 * sv[g] + m2 * cv[g];
            tg[i] = m3;
        }
        if (g >= 5) {
            float R[9], T[3];
#pragma unroll
            for (int i = 0; i < 3; i++) {
#pragma unroll
                for (int j = 0; j < 3; j++)
                    R[i * 3 + j] = prevR[i * 3 + 0] * rg[j]
                                 + prevR[i * 3 + 1] * rg[3 + j]
                                 + prevR[i * 3 + 2] * rg[6 + j];
                T[i] = prevR[i * 3 + 0] * tg[0] + prevR[i * 3 + 1] * tg[1]
                     + prevR[i * 3 + 2] * tg[2] + prevT[i];
            }
#pragma unroll
            for (int i = 0; i < 9; i++) rg[i] = R[i];
#pragma unroll
            for (int i = 0; i < 3; i++) tg[i] = T[i];
        }
        if (g >= 4) {
#pragma unroll
            for (int i = 0; i < 9; i++) prevR[i] = rg[i];
#pragma unroll
            for (int i = 0; i < 3; i++) prevT[i] = tg[i];
        }
        float R[9], T[3];
#pragma unroll
        for (int i = 0; i < 3; i++) {
#pragma unroll
            for (int j = 0; j < 3; j++)
                R[i * 3 + j] = rb[i * 3 + 0] * rg[j] + rb[i * 3 + 1] * rg[3 + j]
                             + rb[i * 3 + 2] * rg[6 + j];
        }
        T[0] = rb[0] * tg[0] + rb[1] * tg[1] + rb[2] * tg[2] + tb0;
        T[1] = rb[3] * tg[0] + rb[4] * tg[1] + rb[5] * tg[2] + tb1;
        T[2] = rb[6] * tg[0] + rb[7] * tg[1] + rb[8] * tg[2] + tb2;

#pragma unroll
        for (int i = 0; i < 9; i++)
            out_rg[(size_t)r * 72 + g * 9 + i] = R[i];
#pragma unroll
        for (int i = 0; i < 3; i++)
            out_tg[(size_t)r * 24 + g * 3 + i] = T[i];

        float* rt = sRT + tid * 97 + g * 12;
#pragma unroll
        for (int i = 0; i < 9; i++) rt[i] = R[i];
#pragma unroll
        for (int i = 0; i < 3; i++) rt[9 + i] = T[i];
    }

#pragma unroll
    for (int a = 0; a < 14; a++) {
        int ga = gidx[at * 14 + a];
        float mk = amask[at * 14 + a];
        float l0 = lit[((size_t)at * 14 + a) * 3 + 0];
        float l1 = lit[((size_t)at * 14 + a) * 3 + 1];
        float l2 = lit[((size_t)at * 14 + a) * 3 + 2];
        const float* rt = sRT + tid * 97 + ga * 12;
        float p0 = (rt[0] * l0 + rt[1] * l1 + rt[2] * l2 + rt[9])  * mk;
        float p1 = (rt[3] * l0 + rt[4] * l1 + rt[5] * l2 + rt[10]) * mk;
        float p2 = (rt[6] * l0 + rt[7] * l1 + rt[8] * l2 + rt[11]) * mk;
        out_pos[(size_t)r * 42 + a * 3 + 0] = p0;
        out_pos[(size_t)r * 42 + a * 3 + 1] = p1;
        out_pos[(size_t)r * 42 + a * 3 + 2] = p2;
    }
}

// ---------------------------------------------------------------------------
extern "C" void kernel_launch(void* const* d_in, const int* in_sizes, int n_in,
                              void* d_out, int out_size)
{
    const float* affine = (const float*)d_in[0];
    const float* rep0   = (const float*)d_in[1];
    const float* rep1   = (const float*)d_in[2];
    const int*   aatype = (const int*)d_in[3];
    const float* w_in0  = (const float*)d_in[4];
    const float* b_in0  = (const float*)d_in[5];
    const float* w_in1  = (const float*)d_in[6];
    const float* b_in1  = (const float*)d_in[7];
    const float* Wr1    = (const float*)d_in[8];
    const float* br1    = (const float*)d_in[9];
    const float* Wr2    = (const float*)d_in[10];
    const float* br2    = (const float*)d_in[11];
    const float* w_ang  = (const float*)d_in[12];
    const float* b_ang  = (const float*)d_in[13];
    const float* frames = (const float*)d_in[14];
    const int*   gidx   = (const int*)d_in[15];
    const float* amask  = (const float*)d_in[16];
    const float* lit    = (const float*)d_in[17];
    float* out = (float*)d_out;

    const int n = in_sizes[0] / 7;

    static bool attr_set = false;
    if (!attr_set) {
        cudaFuncSetAttribute(fused_all, cudaFuncAttributeMaxDynamicSharedMemorySize, SMEM_TOTAL);
        attr_set = true;
    }

    pack_weights<<<81, 256>>>(w_in0, w_in1, Wr1, Wr2, w_ang);
    fused_all<<<n / 64, 256, SMEM_TOTAL>>>(rep0, rep1, b_in0, b_in1, br1, br2, b_ang,
                                           affine, aatype, frames, gidx, amask, lit,
                                           out, n);
}